// round 7
// baseline (speedup 1.0000x reference)
#include <cuda_runtime.h>
#include <math.h>
#include <stdint.h>

#define NTT 730
#define NSS 2000
#define NHH 16
#define NRR 15
#define NSH (NSS*NHH)          // 32000
#define NTS (NTT*NSS)          // 1460000

#define L2E2 2.8853900817779268f   // 2*log2(e)

// -------- scratch (device globals; no allocation) --------
__device__ __align__(128) float  g_b1T[NSS*256];     // [s][k]
__device__ __align__(128) float  g_b2T[NSS*256];
__device__ __align__(128) float4 g_wc4[256];         // first-layer x-coeffs
__device__ __align__(128) float2 g_W2p[32*4*49];     // tf32-packed W2 pairs (k,k+4)
__device__ __align__(128) float  g_sbias[48];
__device__ __align__(128) float g_k1[NSH], g_k2[NSH], g_k23[NSH], g_k3[NSH];
__device__ __align__(128) float g_gl[NSH], g_qb[NSH], g_ge1[NSH], g_ge2[NSH];
__device__ __align__(128) float g_cw[NSH*NRR];
__device__ __align__(128) float g_vi[(size_t)NTT*NSH];
__device__ __align__(128) float g_vk[(size_t)NTT*NSH];
__device__ __align__(128) float g_vm[(size_t)NTT*NSH];
__device__ __align__(128) float4 g_PPE[NTS];         // {Ps, Pl, E, 0}
__device__ __align__(128) float g_QT[(size_t)NTT*NSH];

__device__ __forceinline__ float tanh_fast(float x) {
    float e = __expf(2.f * x);
    return 1.f - __fdividef(2.f, e + 1.f);
}
__device__ __forceinline__ float sigmoid_f(float x) {
    return __fdividef(1.f, 1.f + __expf(-x));
}
__device__ __forceinline__ float hsig(float x) {
    return __saturatef(x * (1.f/6.f) + 0.5f);
}
__device__ __forceinline__ float tanhaf(float x) {
    float r; asm("tanh.approx.f32 %0, %1;" : "=f"(r) : "f"(x));
    return r;
}
__device__ __forceinline__ float ex2f(float t) {
    float e; asm("ex2.approx.f32 %0, %1;" : "=f"(e) : "f"(t));
    return e;
}
__device__ __forceinline__ uint32_t cvt_tf32(float x) {
    uint32_t r; asm("cvt.rna.tf32.f32 %0, %1;" : "=r"(r) : "f"(x));
    return r;
}
__device__ __forceinline__ void mma8(float* d, const uint32_t* a, float2 b) {
    uint32_t b0 = __float_as_uint(b.x), b1 = __float_as_uint(b.y);
    asm("mma.sync.aligned.m16n8k8.row.col.f32.tf32.tf32.f32 "
        "{%0,%1,%2,%3}, {%4,%5,%6,%7}, {%8,%9}, {%0,%1,%2,%3};"
        : "+f"(d[0]), "+f"(d[1]), "+f"(d[2]), "+f"(d[3])
        : "r"(a[0]), "r"(a[1]), "r"(a[2]), "r"(a[3]), "r"(b0), "r"(b1));
}

// =====================================================================
// Kernel A: per-basin MLPs (w, wR) + transposed bases
// =====================================================================
__global__ __launch_bounds__(256) void prep_kernel(
    const float* __restrict__ xc,
    const float* __restrict__ fc_W1,  const float* __restrict__ fc_b1,
    const float* __restrict__ fc_W2,  const float* __restrict__ fc_b2,
    const float* __restrict__ fcR_W1, const float* __restrict__ fcR_b1,
    const float* __restrict__ fcR_W2, const float* __restrict__ fcR_b2,
    const float* __restrict__ fcT1_W1,const float* __restrict__ fcT1_b1,
    const float* __restrict__ fcT2_W1,const float* __restrict__ fcT2_b1)
{
    int s = blockIdx.x;
    int tid = threadIdx.x;
    __shared__ float sxc[32];
    __shared__ float sh_h[256], sh_hR[256];
    __shared__ float sh_w[160], sh_wR[240];
    __shared__ float sh_ga[16];

    if (tid < 32) sxc[tid] = xc[s*32 + tid];
    __syncthreads();

    {
        int k = tid;
        float a0 = fc_b1[k], a1 = fcR_b1[k], a2 = fcT1_b1[k], a3 = fcT2_b1[k];
        #pragma unroll
        for (int g = 0; g < 32; g++) {
            float xg = sxc[g];
            a0 += xg * fc_W1 [k*32 + g];
            a1 += xg * fcR_W1[k*32 + g];
            a2 += xg * fcT1_W1[k*33 + 1 + g];
            a3 += xg * fcT2_W1[k*35 + 3 + g];
        }
        sh_h[k]  = tanh_fast(a0);
        sh_hR[k] = tanh_fast(a1);
        g_b1T[s*256 + k] = a2;
        g_b2T[s*256 + k] = a3;
    }
    __syncthreads();

    int warp = tid >> 5, lane = tid & 31;
    for (int o = warp; o < 400; o += 8) {
        float sum = 0.f;
        if (o < 160) {
            const float* w = fc_W2 + o*256;
            for (int k = lane; k < 256; k += 32) sum += sh_h[k] * w[k];
        } else {
            const float* w = fcR_W2 + (o-160)*256;
            for (int k = lane; k < 256; k += 32) sum += sh_hR[k] * w[k];
        }
        #pragma unroll
        for (int off = 16; off; off >>= 1) sum += __shfl_down_sync(0xffffffffu, sum, off);
        if (lane == 0) {
            if (o < 160) sh_w[o] = sum + fc_b2[o];
            else         sh_wR[o-160] = sum + fcR_b2[o-160];
        }
    }
    __syncthreads();

    if (tid < 16) {
        int h = tid, g = s*16 + h;
        g_k1 [g] = sigmoid_f(sh_w[ 16 + h]);
        g_k2 [g] = sigmoid_f(sh_w[ 32 + h]);
        g_k23[g] = sigmoid_f(sh_w[ 48 + h]);
        g_k3 [g] = sigmoid_f(sh_w[ 64 + h]) * 0.1f;
        g_gl [g] = __expf(sh_w[ 80 + h]) * 2.f;
        g_qb [g] = fmaxf(sh_w[112 + h], 0.f);
        g_ge1[g] = fmaxf(sh_w[128 + h], 0.f);
        g_ge2[g] = fmaxf(sh_w[144 + h], 0.f);
        float m = -1e30f;
        #pragma unroll
        for (int j = 0; j < 16; j++) m = fmaxf(m, sh_w[96 + j]);
        float den = 0.f;
        #pragma unroll
        for (int j = 0; j < 16; j++) den += __expf(sh_w[96 + j] - m);
        sh_ga[h] = __fdividef(__expf(sh_w[96 + h] - m), den);
    }
    __syncthreads();

    if (tid < 240) {
        int h = tid / 15, d = tid - h*15;
        g_cw[(s*16 + h)*15 + d] = sh_ga[h] * fmaxf(sh_wR[h*15 + (14 - d)], 0.f);
    }
}

// =====================================================================
// Kernel A2: pack W2 into tf32 (k,k+4) float2 pairs + wc/bias tables
// =====================================================================
__global__ __launch_bounds__(256) void pack_kernel(
    const float* __restrict__ fcT1_W1, const float* __restrict__ fcT2_W1,
    const float* __restrict__ fcT1_W2, const float* __restrict__ fcT1_b2,
    const float* __restrict__ fcT2_W2, const float* __restrict__ fcT2_b2)
{
    int tid = threadIdx.x;
    {
        int k = tid;
        g_wc4[k] = make_float4(fcT1_W1[k*33],
                               fcT2_W1[k*35],
                               fcT2_W1[k*35 + 1],
                               fcT2_W1[k*35 + 2]);
    }
    if (tid < 48) g_sbias[tid] = (tid < 32) ? fcT1_b2[tid] : fcT2_b2[tid - 32];

    for (int idx = tid; idx < 32*4*48; idx += 256) {
        int j = idx / 192, rem = idx - j*192;
        int c = rem / 48,  o  = rem - c*48;
        int k0 = 8*j + c, k1 = k0 + 4;
        float w0 = (o < 32) ? fcT1_W2[o*256 + k0] : fcT2_W2[(o-32)*256 + k0];
        float w1 = (o < 32) ? fcT1_W2[o*256 + k1] : fcT2_W2[(o-32)*256 + k1];
        g_W2p[(j*4 + c)*49 + o] =
            make_float2(__uint_as_float(cvt_tf32(w0)), __uint_as_float(cvt_tf32(w1)));
    }
}

// =====================================================================
// Kernel B: tensor-core MLP with tanh.approx. warp = 16 t x 1 basin.
// =====================================================================
#define SMEM_W2P_F (32*4*49*2)          // 12544 floats
#define SMEM_MLP_BYTES ((SMEM_W2P_F + 256*4 + 8*512 + 48) * 4)   // 70848

__global__ __launch_bounds__(256, 2) void mlp_kernel(const float* __restrict__ x)
{
    extern __shared__ float smem[];
    float2* sW2p  = (float2*)smem;                    // [32*4*49]
    float4* swc   = (float4*)(smem + SMEM_W2P_F);     // [256]
    float*  sbase = smem + SMEM_W2P_F + 256*4;        // [8][512]
    float*  sbias = sbase + 8*512;                    // [48]

    int tid = threadIdx.x;
    int w = tid >> 5, lane = tid & 31;
    int c = lane & 3, r = lane >> 2;

    {
        const uint4* src = (const uint4*)g_W2p;
        uint4* dst = (uint4*)sW2p;
        for (int i = tid; i < SMEM_W2P_F/4; i += 256) dst[i] = src[i];
        swc[tid] = g_wc4[tid];
        if (tid < 48) sbias[tid] = g_sbias[tid];
    }
    int s = blockIdx.y*8 + w;
    {
        float* sb = sbase + w*512;
        const float4* b1s = (const float4*)(g_b1T + s*256);
        const float4* b2s = (const float4*)(g_b2T + s*256);
        for (int i = lane; i < 64; i += 32) {
            ((float4*)sb)[i]        = b1s[i];
            ((float4*)(sb+256))[i]  = b2s[i];
        }
    }
    __syncthreads();

    int t0 = blockIdx.x * 16;
    int tA = t0 + r;              // always < NTT (max 727)
    int tB = tA + 8;              // may overflow on last tile
    int tBl = (tB < NTT) ? tB : (NTT-1);

    const float* xA = x + (size_t)(tA *NSS + s)*6;
    const float* xB = x + (size_t)(tBl*NSS + s)*6;
    float PA = xA[0], EA = xA[1], T1A = xA[2], T2A = xA[3], RA = xA[4], LA = xA[5];
    float PB = xB[0], EB = xB[1], T1B = xB[2], T2B = xB[3], RB = xB[4], LB = xB[5];

    if (c == 0) {
        {
            float dn = T2A - T1A;
            float rr = (T1A + T2A) / (dn == 0.f ? 1.f : dn);
            rr = fminf(fmaxf(rr, -1.f), 1.f);
            if ((T1A >= 0.f) || (T2A <= 0.f)) rr = 0.f;
            float vp = 1.f - acosf(rr) / 3.1415f;
            if (T1A >= 0.f) vp = 1.f;
            if (T2A <= 0.f) vp = 0.f;
            g_PPE[tA*NSS + s] = make_float4(PA * (1.f - vp), PA * vp, EA, 0.f);
        }
        if (tB < NTT) {
            float dn = T2B - T1B;
            float rr = (T1B + T2B) / (dn == 0.f ? 1.f : dn);
            rr = fminf(fmaxf(rr, -1.f), 1.f);
            if ((T1B >= 0.f) || (T2B <= 0.f)) rr = 0.f;
            float vp = 1.f - acosf(rr) / 3.1415f;
            if (T1B >= 0.f) vp = 1.f;
            if (T2B <= 0.f) vp = 0.f;
            g_PPE[tB*NSS + s] = make_float4(PB * (1.f - vp), PB * vp, EB, 0.f);
        }
    }

    float dd[6][4];
    #pragma unroll
    for (int g = 0; g < 6; g++)
        #pragma unroll
        for (int i = 0; i < 4; i++) dd[g][i] = 0.f;

    const float* sb1 = sbase + w*512;
    const float* sb2 = sb1 + 256;

    #pragma unroll 2
    for (int j = 0; j < 32; j++) {
        int k0 = j*8 + c;
        float b1k0 = sb1[k0], b1k1 = sb1[k0+4];
        float b2k0 = sb2[k0], b2k1 = sb2[k0+4];
        float4 w0 = swc[k0], w1 = swc[k0+4];

        uint32_t aa1[4], aa2[4];
        aa1[0] = cvt_tf32(tanhaf(fmaf(LA, w0.x, b1k0)));
        aa1[1] = cvt_tf32(tanhaf(fmaf(LB, w0.x, b1k0)));
        aa1[2] = cvt_tf32(tanhaf(fmaf(LA, w1.x, b1k1)));
        aa1[3] = cvt_tf32(tanhaf(fmaf(LB, w1.x, b1k1)));
        aa2[0] = cvt_tf32(tanhaf(fmaf(RA, w0.y, fmaf(T1A, w0.z, fmaf(T2A, w0.w, b2k0)))));
        aa2[1] = cvt_tf32(tanhaf(fmaf(RB, w0.y, fmaf(T1B, w0.z, fmaf(T2B, w0.w, b2k0)))));
        aa2[2] = cvt_tf32(tanhaf(fmaf(RA, w1.y, fmaf(T1A, w1.z, fmaf(T2A, w1.w, b2k1)))));
        aa2[3] = cvt_tf32(tanhaf(fmaf(RB, w1.y, fmaf(T1B, w1.z, fmaf(T2B, w1.w, b2k1)))));

        const float2* Wrow = sW2p + (j*4 + c)*49;
        #pragma unroll
        for (int g = 0; g < 4; g++) mma8(dd[g], aa1, Wrow[8*g + r]);
        #pragma unroll
        for (int g = 4; g < 6; g++) mma8(dd[g], aa2, Wrow[8*g + r]);
    }

    #pragma unroll
    for (int g = 0; g < 6; g++) {
        int o = 8*g + 2*c;
        float bi0 = sbias[o], bi1 = sbias[o+1];
        float vA0 = dd[g][0] + bi0, vA1 = dd[g][1] + bi1;
        float vB0 = dd[g][2] + bi0, vB1 = dd[g][3] + bi1;
        float2 oA, oB;
        float* arr;
        if (g < 4) {
            oA = make_float2(hsig(vA0), hsig(vA1));
            oB = make_float2(hsig(vB0), hsig(vB1));
            arr = (g < 2) ? g_vi : g_vk;
        } else {
            oA = make_float2(ex2f(vA0*L2E2), ex2f(vA1*L2E2));
            oB = make_float2(ex2f(vB0*L2E2), ex2f(vB1*L2E2));
            arr = g_vm;
        }
        int h = o & 15;
        *(float2*)(arr + (size_t)tA*NSH + s*16 + h) = oA;
        if (tB < NTT)
            *(float2*)(arr + (size_t)tB*NSH + s*16 + h) = oB;
    }
}

// =====================================================================
// Kernel C: sequential reservoir scan; thread = (s,h).
// Depth-8 software pipeline, __ldg loads, packed PPE.
// =====================================================================
#define SCP 8
__global__ __launch_bounds__(64) void scan_kernel()
{
    int g = blockIdx.x * 64 + threadIdx.x;
    if (g >= NSH) return;
    int s = g >> 4;
    float k1 = g_k1[g], k2 = g_k2[g], k23 = g_k23[g], k3 = g_k3[g];
    float gl = g_gl[g], qb = g_qb[g], ge1 = g_ge1[g], ge2 = g_ge2[g];
    float S0 = 0.f, Sv = 0.f, S2 = 0.f, S3 = 0.f;

    float b_vi[SCP], b_vk[SCP], b_vm[SCP];
    float4 b_ppe[SCP];
    #pragma unroll
    for (int i = 0; i < SCP; i++) {
        size_t tg = (size_t)i*NSH + g;
        b_vi[i] = __ldg(g_vi + tg);
        b_vk[i] = __ldg(g_vk + tg);
        b_vm[i] = __ldg(g_vm + tg);
        b_ppe[i] = __ldg(g_PPE + i*NSS + s);
    }

    #pragma unroll 4
    for (int t = 0; t < NTT; t++) {
        int slot = t & (SCP-1);
        float Ps = b_ppe[slot].x, Pl = b_ppe[slot].y, E = b_ppe[slot].z;
        float vi = b_vi[slot], vk = b_vk[slot], vm = b_vm[slot];

        int tn = t + SCP;
        if (tn < NTT) {
            size_t tg = (size_t)tn*NSH + g;
            b_vi[slot] = __ldg(g_vi + tg);
            b_vk[slot] = __ldg(g_vk + tg);
            b_vm[slot] = __ldg(g_vm + tg);
            b_ppe[slot] = __ldg(g_PPE + tn*NSS + s);
        }

        float H0  = S0 + Ps;
        float qSm = fminf(H0, vm);
        float Hv  = fmaxf(Sv + Pl*(1.f - vi) - E*ge1, 0.f);
        float qv  = Sv * vk;
        float H2  = fmaxf(S2 + qSm + qv - E*ge2 + Pl*vi, 0.f);
        float x1  = H2 - gl;
        float Q1  = (x1 > 0.f) ? exp2f(k1 * __log2f(x1)) : 0.f;
        float q2  = fminf(H2, gl) * k2;
        float Q2  = q2 * (1.f - k23);
        float H3  = S3 + q2 * k23;
        float Q3  = H3 * k3 + qb;

        S0 = H0 - qSm;
        Sv = Hv - qv;
        S2 = H2 - Q1 - q2;
        S3 = H3 - Q3;
        g_QT[(size_t)t*NSH + g] = Q1 + Q2 + Q3;
    }
}

// =====================================================================
// Kernel D: causal depthwise conv + head-sum, register-blocked 4 t/thread
// =====================================================================
#define CVT 192
#define CVS 788
__global__ __launch_bounds__(CVT) void conv_kernel(float* __restrict__ out)
{
    __shared__ float shQ[16*CVS];
    __shared__ float shc[NHH*NRR];
    int s = blockIdx.x;
    int tid = threadIdx.x;

    for (int i = tid; i < 16*CVS; i += CVT) {
        int j = i >> 4, h = i & 15;
        int t = j - 14;
        shQ[h*CVS + j] = (t >= 0 && t < NTT)
            ? g_QT[(size_t)t*NSH + s*16 + h] : 0.f;
    }
    for (int i = tid; i < 240; i += CVT) shc[i] = g_cw[s*240 + i];
    __syncthreads();

    int tb = tid * 4;
    if (tb < NTT) {
        float acc0 = 0.f, acc1 = 0.f, acc2 = 0.f, acc3 = 0.f;
        #pragma unroll
        for (int h = 0; h < 16; h++) {
            const float4* qw = (const float4*)(shQ + h*CVS + tb);
            float wv[20];
            #pragma unroll
            for (int v = 0; v < 5; v++) {
                float4 q4 = qw[v];
                wv[4*v+0] = q4.x; wv[4*v+1] = q4.y; wv[4*v+2] = q4.z; wv[4*v+3] = q4.w;
            }
            #pragma unroll
            for (int d = 0; d < 15; d++) {
                float cc = shc[h*15 + d];
                acc0 += wv[14 - d] * cc;
                acc1 += wv[15 - d] * cc;
                acc2 += wv[16 - d] * cc;
                acc3 += wv[17 - d] * cc;
            }
        }
        out[(tb+0)*NSS + s] = acc0;
        if (tb+1 < NTT) out[(tb+1)*NSS + s] = acc1;
        if (tb+2 < NTT) out[(tb+2)*NSS + s] = acc2;
        if (tb+3 < NTT) out[(tb+3)*NSS + s] = acc3;
    }
}

// =====================================================================
extern "C" void kernel_launch(void* const* d_in, const int* in_sizes, int n_in,
                              void* d_out, int out_size)
{
    const float* x       = (const float*)d_in[0];
    const float* xc      = (const float*)d_in[1];
    const float* fc_W1   = (const float*)d_in[2];
    const float* fc_b1   = (const float*)d_in[3];
    const float* fc_W2   = (const float*)d_in[4];
    const float* fc_b2   = (const float*)d_in[5];
    const float* fcR_W1  = (const float*)d_in[6];
    const float* fcR_b1  = (const float*)d_in[7];
    const float* fcR_W2  = (const float*)d_in[8];
    const float* fcR_b2  = (const float*)d_in[9];
    const float* fcT1_W1 = (const float*)d_in[10];
    const float* fcT1_b1 = (const float*)d_in[11];
    const float* fcT1_W2 = (const float*)d_in[12];
    const float* fcT1_b2 = (const float*)d_in[13];
    const float* fcT2_W1 = (const float*)d_in[14];
    const float* fcT2_b1 = (const float*)d_in[15];
    const float* fcT2_W2 = (const float*)d_in[16];
    const float* fcT2_b2 = (const float*)d_in[17];

    cudaFuncSetAttribute(mlp_kernel, cudaFuncAttributeMaxDynamicSharedMemorySize,
                         SMEM_MLP_BYTES);

    prep_kernel<<<NSS, 256>>>(xc, fc_W1, fc_b1, fc_W2, fc_b2,
                              fcR_W1, fcR_b1, fcR_W2, fcR_b2,
                              fcT1_W1, fcT1_b1, fcT2_W1, fcT2_b1);

    pack_kernel<<<1, 256>>>(fcT1_W1, fcT2_W1, fcT1_W2, fcT1_b2, fcT2_W2, fcT2_b2);

    dim3 gB((NTT + 15)/16, NSS/8);
    mlp_kernel<<<gB, 256, SMEM_MLP_BYTES>>>(x);

    scan_kernel<<<(NSH + 63)/64, 64>>>();

    conv_kernel<<<NSS, CVT>>>((float*)d_out);
}

// round 8
// speedup vs baseline: 1.4367x; 1.4367x over previous
#include <cuda_runtime.h>
#include <math.h>
#include <stdint.h>

#define NTT 730
#define NSS 2000
#define NHH 16
#define NRR 15
#define NSH (NSS*NHH)          // 32000
#define NTS (NTT*NSS)          // 1460000

#define L2E2 2.8853900817779268f   // 2*log2(e)
#define W2S 132                    // float2 row stride: 132 mod 16 == 4 -> conflict-free

// -------- scratch (device globals; no allocation) --------
__device__ __align__(128) float  g_b1T[NSS*256];     // [s][k]
__device__ __align__(128) float  g_b2T[NSS*256];
__device__ __align__(128) float4 g_wc4[256];         // first-layer x-coeffs
__device__ __align__(128) float2 g_W2T[48*W2S];      // tf32 pairs, [o][j*4+c]
__device__ __align__(128) float  g_sbias[48];
__device__ __align__(128) float g_k1[NSH], g_k2[NSH], g_k23[NSH], g_k3[NSH];
__device__ __align__(128) float g_gl[NSH], g_qb[NSH], g_ge1[NSH], g_ge2[NSH];
__device__ __align__(128) float g_cw[NSH*NRR];
__device__ __align__(128) float g_vi[(size_t)NTT*NSH];
__device__ __align__(128) float g_vk[(size_t)NTT*NSH];
__device__ __align__(128) float g_vm[(size_t)NTT*NSH];
__device__ __align__(128) float4 g_PPE[NTS];         // {Ps, Pl, E, 0}
__device__ __align__(128) float g_QT[(size_t)NTT*NSH];

__device__ __forceinline__ float tanh_fast(float x) {
    float e = __expf(2.f * x);
    return 1.f - __fdividef(2.f, e + 1.f);
}
__device__ __forceinline__ float sigmoid_f(float x) {
    return __fdividef(1.f, 1.f + __expf(-x));
}
__device__ __forceinline__ float hsig(float x) {
    return __saturatef(x * (1.f/6.f) + 0.5f);
}
__device__ __forceinline__ float tanhaf(float x) {
    float r; asm("tanh.approx.f32 %0, %1;" : "=f"(r) : "f"(x));
    return r;
}
__device__ __forceinline__ float ex2f(float t) {
    float e; asm("ex2.approx.f32 %0, %1;" : "=f"(e) : "f"(t));
    return e;
}
__device__ __forceinline__ uint32_t cvt_tf32(float x) {
    uint32_t r; asm("cvt.rna.tf32.f32 %0, %1;" : "=r"(r) : "f"(x));
    return r;
}
__device__ __forceinline__ void mma8(float* d, const uint32_t* a, float2 b) {
    uint32_t b0 = __float_as_uint(b.x), b1 = __float_as_uint(b.y);
    asm("mma.sync.aligned.m16n8k8.row.col.f32.tf32.tf32.f32 "
        "{%0,%1,%2,%3}, {%4,%5,%6,%7}, {%8,%9}, {%0,%1,%2,%3};"
        : "+f"(d[0]), "+f"(d[1]), "+f"(d[2]), "+f"(d[3])
        : "r"(a[0]), "r"(a[1]), "r"(a[2]), "r"(a[3]), "r"(b0), "r"(b1));
}

// =====================================================================
// Kernel A: per-basin MLPs (w, wR) + transposed bases
// =====================================================================
__global__ __launch_bounds__(256) void prep_kernel(
    const float* __restrict__ xc,
    const float* __restrict__ fc_W1,  const float* __restrict__ fc_b1,
    const float* __restrict__ fc_W2,  const float* __restrict__ fc_b2,
    const float* __restrict__ fcR_W1, const float* __restrict__ fcR_b1,
    const float* __restrict__ fcR_W2, const float* __restrict__ fcR_b2,
    const float* __restrict__ fcT1_W1,const float* __restrict__ fcT1_b1,
    const float* __restrict__ fcT2_W1,const float* __restrict__ fcT2_b1)
{
    int s = blockIdx.x;
    int tid = threadIdx.x;
    __shared__ float sxc[32];
    __shared__ float sh_h[256], sh_hR[256];
    __shared__ float sh_w[160], sh_wR[240];
    __shared__ float sh_ga[16];

    if (tid < 32) sxc[tid] = xc[s*32 + tid];
    __syncthreads();

    {
        int k = tid;
        float a0 = fc_b1[k], a1 = fcR_b1[k], a2 = fcT1_b1[k], a3 = fcT2_b1[k];
        #pragma unroll
        for (int g = 0; g < 32; g++) {
            float xg = sxc[g];
            a0 += xg * fc_W1 [k*32 + g];
            a1 += xg * fcR_W1[k*32 + g];
            a2 += xg * fcT1_W1[k*33 + 1 + g];
            a3 += xg * fcT2_W1[k*35 + 3 + g];
        }
        sh_h[k]  = tanh_fast(a0);
        sh_hR[k] = tanh_fast(a1);
        g_b1T[s*256 + k] = a2;
        g_b2T[s*256 + k] = a3;
    }
    __syncthreads();

    int warp = tid >> 5, lane = tid & 31;
    for (int o = warp; o < 400; o += 8) {
        float sum = 0.f;
        if (o < 160) {
            const float* w = fc_W2 + o*256;
            for (int k = lane; k < 256; k += 32) sum += sh_h[k] * w[k];
        } else {
            const float* w = fcR_W2 + (o-160)*256;
            for (int k = lane; k < 256; k += 32) sum += sh_hR[k] * w[k];
        }
        #pragma unroll
        for (int off = 16; off; off >>= 1) sum += __shfl_down_sync(0xffffffffu, sum, off);
        if (lane == 0) {
            if (o < 160) sh_w[o] = sum + fc_b2[o];
            else         sh_wR[o-160] = sum + fcR_b2[o-160];
        }
    }
    __syncthreads();

    if (tid < 16) {
        int h = tid, g = s*16 + h;
        g_k1 [g] = sigmoid_f(sh_w[ 16 + h]);
        g_k2 [g] = sigmoid_f(sh_w[ 32 + h]);
        g_k23[g] = sigmoid_f(sh_w[ 48 + h]);
        g_k3 [g] = sigmoid_f(sh_w[ 64 + h]) * 0.1f;
        g_gl [g] = __expf(sh_w[ 80 + h]) * 2.f;
        g_qb [g] = fmaxf(sh_w[112 + h], 0.f);
        g_ge1[g] = fmaxf(sh_w[128 + h], 0.f);
        g_ge2[g] = fmaxf(sh_w[144 + h], 0.f);
        float m = -1e30f;
        #pragma unroll
        for (int j = 0; j < 16; j++) m = fmaxf(m, sh_w[96 + j]);
        float den = 0.f;
        #pragma unroll
        for (int j = 0; j < 16; j++) den += __expf(sh_w[96 + j] - m);
        sh_ga[h] = __fdividef(__expf(sh_w[96 + h] - m), den);
    }
    __syncthreads();

    if (tid < 240) {
        int h = tid / 15, d = tid - h*15;
        g_cw[(s*16 + h)*15 + d] = sh_ga[h] * fmaxf(sh_wR[h*15 + (14 - d)], 0.f);
    }
}

// =====================================================================
// Kernel A2: pack W2 into [o][j*4+c] tf32 pairs + wc/bias tables
// =====================================================================
__global__ __launch_bounds__(256) void pack_kernel(
    const float* __restrict__ fcT1_W1, const float* __restrict__ fcT2_W1,
    const float* __restrict__ fcT1_W2, const float* __restrict__ fcT1_b2,
    const float* __restrict__ fcT2_W2, const float* __restrict__ fcT2_b2)
{
    int tid = threadIdx.x;
    {
        int k = tid;
        g_wc4[k] = make_float4(fcT1_W1[k*33],
                               fcT2_W1[k*35],
                               fcT2_W1[k*35 + 1],
                               fcT2_W1[k*35 + 2]);
    }
    if (tid < 48) g_sbias[tid] = (tid < 32) ? fcT1_b2[tid] : fcT2_b2[tid - 32];

    // pad columns 128..131 with zeros, fill the rest
    for (int idx = tid; idx < 48*W2S; idx += 256) {
        int o = idx / W2S, km = idx - o*W2S;
        float2 v = make_float2(0.f, 0.f);
        if (km < 128) {
            int j = km >> 2, c = km & 3;
            int k0 = 8*j + c, k1 = k0 + 4;
            float w0 = (o < 32) ? fcT1_W2[o*256 + k0] : fcT2_W2[(o-32)*256 + k0];
            float w1 = (o < 32) ? fcT1_W2[o*256 + k1] : fcT2_W2[(o-32)*256 + k1];
            v = make_float2(__uint_as_float(cvt_tf32(w0)), __uint_as_float(cvt_tf32(w1)));
        }
        g_W2T[idx] = v;
    }
}

// =====================================================================
// Kernel B: tensor-core MLP. warp = 32 timesteps x 1 basin (2 mma tiles).
// Conflict-free W2 layout; bases packed as float2.
// =====================================================================
#define SMEM_MLP_BYTES (48*W2S*8 + 256*16 + 8*256*8 + 48*4)   // 71360

__global__ __launch_bounds__(256, 2) void mlp_kernel(const float* __restrict__ x)
{
    extern __shared__ float smem[];
    float2* sW2T  = (float2*)smem;                          // [48*W2S]
    float4* swc   = (float4*)(smem + 48*W2S*2);             // [256]
    float2* sb12  = (float2*)(swc + 256);                   // [8][256] {b1,b2}
    float*  sbias = (float*)(sb12 + 8*256);                 // [48]

    int tid = threadIdx.x;
    int w = tid >> 5, lane = tid & 31;
    int c = lane & 3, r = lane >> 2;

    {
        const uint4* src = (const uint4*)g_W2T;
        uint4* dst = (uint4*)sW2T;
        for (int i = tid; i < 48*W2S/2; i += 256) dst[i] = src[i];
        swc[tid] = g_wc4[tid];
        if (tid < 48) sbias[tid] = g_sbias[tid];
    }
    int s = blockIdx.y*8 + w;
    {
        const float* b1s = g_b1T + s*256;
        const float* b2s = g_b2T + s*256;
        float2* sb = sb12 + w*256;
        for (int k = lane; k < 256; k += 32)
            sb[k] = make_float2(b1s[k], b2s[k]);
    }
    __syncthreads();

    int t0 = blockIdx.x * 32;
    int tA = t0 + r;              // < 730 always
    int tB = tA + 8;              // < 730 always
    int tC = tA + 16;             // < 730 always
    int tD = tA + 24;             // may overflow on last tile
    bool vD = (tD < NTT);
    int tDl = vD ? tD : (NTT-1);

    const float* xA = x + (size_t)(tA *NSS + s)*6;
    const float* xB = x + (size_t)(tB *NSS + s)*6;
    const float* xC = x + (size_t)(tC *NSS + s)*6;
    const float* xD = x + (size_t)(tDl*NSS + s)*6;
    float PA = xA[0], EA = xA[1], T1A = xA[2], T2A = xA[3], RA = xA[4], LA = xA[5];
    float PB = xB[0], EB = xB[1], T1B = xB[2], T2B = xB[3], RB = xB[4], LB = xB[5];
    float PC = xC[0], EC = xC[1], T1C = xC[2], T2C = xC[3], RC = xC[4], LC = xC[5];
    float PD = xD[0], ED = xD[1], T1D = xD[2], T2D = xD[3], RD = xD[4], LD = xD[5];

    if (c == 0) {
        #pragma unroll
        for (int q = 0; q < 4; q++) {
            float P  = (q==0)?PA :(q==1)?PB :(q==2)?PC :PD;
            float E  = (q==0)?EA :(q==1)?EB :(q==2)?EC :ED;
            float T1 = (q==0)?T1A:(q==1)?T1B:(q==2)?T1C:T1D;
            float T2 = (q==0)?T2A:(q==1)?T2B:(q==2)?T2C:T2D;
            int   t  = (q==0)?tA :(q==1)?tB :(q==2)?tC :tD;
            if (q == 3 && !vD) break;
            float dn = T2 - T1;
            float rr = (T1 + T2) / (dn == 0.f ? 1.f : dn);
            rr = fminf(fmaxf(rr, -1.f), 1.f);
            if ((T1 >= 0.f) || (T2 <= 0.f)) rr = 0.f;
            float vp = 1.f - acosf(rr) / 3.1415f;
            if (T1 >= 0.f) vp = 1.f;
            if (T2 <= 0.f) vp = 0.f;
            g_PPE[t*NSS + s] = make_float4(P * (1.f - vp), P * vp, E, 0.f);
        }
    }

    float dAB[6][4], dCD[6][4];
    #pragma unroll
    for (int g = 0; g < 6; g++)
        #pragma unroll
        for (int i = 0; i < 4; i++) { dAB[g][i] = 0.f; dCD[g][i] = 0.f; }

    const float2* sb = sb12 + w*256;

    #pragma unroll 1
    for (int j = 0; j < 32; j++) {
        int k0 = j*8 + c;
        float2 b0 = sb[k0];           // {b1, b2} at k0
        float2 b4 = sb[k0 + 4];       // at k0+4
        float4 w0 = swc[k0], w1 = swc[k0+4];

        uint32_t aa1AB[4], aa1CD[4], aa2AB[4], aa2CD[4];
        aa1AB[0] = cvt_tf32(tanhaf(fmaf(LA, w0.x, b0.x)));
        aa1AB[1] = cvt_tf32(tanhaf(fmaf(LB, w0.x, b0.x)));
        aa1AB[2] = cvt_tf32(tanhaf(fmaf(LA, w1.x, b4.x)));
        aa1AB[3] = cvt_tf32(tanhaf(fmaf(LB, w1.x, b4.x)));
        aa1CD[0] = cvt_tf32(tanhaf(fmaf(LC, w0.x, b0.x)));
        aa1CD[1] = cvt_tf32(tanhaf(fmaf(LD, w0.x, b0.x)));
        aa1CD[2] = cvt_tf32(tanhaf(fmaf(LC, w1.x, b4.x)));
        aa1CD[3] = cvt_tf32(tanhaf(fmaf(LD, w1.x, b4.x)));
        aa2AB[0] = cvt_tf32(tanhaf(fmaf(RA, w0.y, fmaf(T1A, w0.z, fmaf(T2A, w0.w, b0.y)))));
        aa2AB[1] = cvt_tf32(tanhaf(fmaf(RB, w0.y, fmaf(T1B, w0.z, fmaf(T2B, w0.w, b0.y)))));
        aa2AB[2] = cvt_tf32(tanhaf(fmaf(RA, w1.y, fmaf(T1A, w1.z, fmaf(T2A, w1.w, b4.y)))));
        aa2AB[3] = cvt_tf32(tanhaf(fmaf(RB, w1.y, fmaf(T1B, w1.z, fmaf(T2B, w1.w, b4.y)))));
        aa2CD[0] = cvt_tf32(tanhaf(fmaf(RC, w0.y, fmaf(T1C, w0.z, fmaf(T2C, w0.w, b0.y)))));
        aa2CD[1] = cvt_tf32(tanhaf(fmaf(RD, w0.y, fmaf(T1D, w0.z, fmaf(T2D, w0.w, b0.y)))));
        aa2CD[2] = cvt_tf32(tanhaf(fmaf(RC, w1.y, fmaf(T1C, w1.z, fmaf(T2C, w1.w, b4.y)))));
        aa2CD[3] = cvt_tf32(tanhaf(fmaf(RD, w1.y, fmaf(T1D, w1.z, fmaf(T2D, w1.w, b4.y)))));

        const float2* Wb = sW2T + (j*4 + c);
        #pragma unroll
        for (int g = 0; g < 4; g++) {
            float2 bw = Wb[(8*g + r)*W2S];
            mma8(dAB[g], aa1AB, bw);
            mma8(dCD[g], aa1CD, bw);
        }
        #pragma unroll
        for (int g = 4; g < 6; g++) {
            float2 bw = Wb[(8*g + r)*W2S];
            mma8(dAB[g], aa2AB, bw);
            mma8(dCD[g], aa2CD, bw);
        }
    }

    #pragma unroll
    for (int g = 0; g < 6; g++) {
        int o = 8*g + 2*c;
        float bi0 = sbias[o], bi1 = sbias[o+1];
        float2 oA, oB, oC, oD;
        float* arr;
        if (g < 4) {
            oA = make_float2(hsig(dAB[g][0]+bi0), hsig(dAB[g][1]+bi1));
            oB = make_float2(hsig(dAB[g][2]+bi0), hsig(dAB[g][3]+bi1));
            oC = make_float2(hsig(dCD[g][0]+bi0), hsig(dCD[g][1]+bi1));
            oD = make_float2(hsig(dCD[g][2]+bi0), hsig(dCD[g][3]+bi1));
            arr = (g < 2) ? g_vi : g_vk;
        } else {
            oA = make_float2(ex2f((dAB[g][0]+bi0)*L2E2), ex2f((dAB[g][1]+bi1)*L2E2));
            oB = make_float2(ex2f((dAB[g][2]+bi0)*L2E2), ex2f((dAB[g][3]+bi1)*L2E2));
            oC = make_float2(ex2f((dCD[g][0]+bi0)*L2E2), ex2f((dCD[g][1]+bi1)*L2E2));
            oD = make_float2(ex2f((dCD[g][2]+bi0)*L2E2), ex2f((dCD[g][3]+bi1)*L2E2));
            arr = g_vm;
        }
        int h = o & 15;
        size_t off = (size_t)s*16 + h;
        *(float2*)(arr + (size_t)tA*NSH + off) = oA;
        *(float2*)(arr + (size_t)tB*NSH + off) = oB;
        *(float2*)(arr + (size_t)tC*NSH + off) = oC;
        if (vD) *(float2*)(arr + (size_t)tD*NSH + off) = oD;
    }
}

// =====================================================================
// Kernel C: sequential reservoir scan; thread = (s,h).
// Depth-4 pipeline (static slots under unroll 4), __ldg, packed PPE.
// =====================================================================
#define SCP 4
__global__ __launch_bounds__(128) void scan_kernel()
{
    int g = blockIdx.x * 128 + threadIdx.x;
    if (g >= NSH) return;
    int s = g >> 4;
    float k1 = g_k1[g], k2 = g_k2[g], k23 = g_k23[g], k3 = g_k3[g];
    float gl = g_gl[g], qb = g_qb[g], ge1 = g_ge1[g], ge2 = g_ge2[g];
    float S0 = 0.f, Sv = 0.f, S2 = 0.f, S3 = 0.f;

    float b_vi[SCP], b_vk[SCP], b_vm[SCP];
    float4 b_ppe[SCP];
    #pragma unroll
    for (int i = 0; i < SCP; i++) {
        size_t tg = (size_t)i*NSH + g;
        b_vi[i] = __ldg(g_vi + tg);
        b_vk[i] = __ldg(g_vk + tg);
        b_vm[i] = __ldg(g_vm + tg);
        b_ppe[i] = __ldg(g_PPE + i*NSS + s);
    }

    #pragma unroll 4
    for (int t = 0; t < NTT; t++) {
        int slot = t & (SCP-1);
        float Ps = b_ppe[slot].x, Pl = b_ppe[slot].y, E = b_ppe[slot].z;
        float vi = b_vi[slot], vk = b_vk[slot], vm = b_vm[slot];

        int tn = t + SCP;
        if (tn < NTT) {
            size_t tg = (size_t)tn*NSH + g;
            b_vi[slot] = __ldg(g_vi + tg);
            b_vk[slot] = __ldg(g_vk + tg);
            b_vm[slot] = __ldg(g_vm + tg);
            b_ppe[slot] = __ldg(g_PPE + tn*NSS + s);
        }

        float H0  = S0 + Ps;
        float qSm = fminf(H0, vm);
        float Hv  = fmaxf(Sv + Pl*(1.f - vi) - E*ge1, 0.f);
        float qv  = Sv * vk;
        float H2  = fmaxf(S2 + qSm + qv - E*ge2 + Pl*vi, 0.f);
        float x1  = H2 - gl;
        float Q1  = (x1 > 0.f) ? exp2f(k1 * __log2f(x1)) : 0.f;
        float q2  = fminf(H2, gl) * k2;
        float Q2  = q2 * (1.f - k23);
        float H3  = S3 + q2 * k23;
        float Q3  = H3 * k3 + qb;

        S0 = H0 - qSm;
        Sv = Hv - qv;
        S2 = H2 - Q1 - q2;
        S3 = H3 - Q3;
        g_QT[(size_t)t*NSH + g] = Q1 + Q2 + Q3;
    }
}

// =====================================================================
// Kernel D: causal depthwise conv + head-sum, register-blocked 4 t/thread
// =====================================================================
#define CVT 192
#define CVS 788
__global__ __launch_bounds__(CVT) void conv_kernel(float* __restrict__ out)
{
    __shared__ float shQ[16*CVS];
    __shared__ float shc[NHH*NRR];
    int s = blockIdx.x;
    int tid = threadIdx.x;

    for (int i = tid; i < 16*CVS; i += CVT) {
        int j = i >> 4, h = i & 15;
        int t = j - 14;
        shQ[h*CVS + j] = (t >= 0 && t < NTT)
            ? g_QT[(size_t)t*NSH + s*16 + h] : 0.f;
    }
    for (int i = tid; i < 240; i += CVT) shc[i] = g_cw[s*240 + i];
    __syncthreads();

    int tb = tid * 4;
    if (tb < NTT) {
        float acc0 = 0.f, acc1 = 0.f, acc2 = 0.f, acc3 = 0.f;
        #pragma unroll
        for (int h = 0; h < 16; h++) {
            const float4* qw = (const float4*)(shQ + h*CVS + tb);
            float wv[20];
            #pragma unroll
            for (int v = 0; v < 5; v++) {
                float4 q4 = qw[v];
                wv[4*v+0] = q4.x; wv[4*v+1] = q4.y; wv[4*v+2] = q4.z; wv[4*v+3] = q4.w;
            }
            #pragma unroll
            for (int d = 0; d < 15; d++) {
                float cc = shc[h*15 + d];
                acc0 += wv[14 - d] * cc;
                acc1 += wv[15 - d] * cc;
                acc2 += wv[16 - d] * cc;
                acc3 += wv[17 - d] * cc;
            }
        }
        out[(tb+0)*NSS + s] = acc0;
        if (tb+1 < NTT) out[(tb+1)*NSS + s] = acc1;
        if (tb+2 < NTT) out[(tb+2)*NSS + s] = acc2;
        if (tb+3 < NTT) out[(tb+3)*NSS + s] = acc3;
    }
}

// =====================================================================
extern "C" void kernel_launch(void* const* d_in, const int* in_sizes, int n_in,
                              void* d_out, int out_size)
{
    const float* x       = (const float*)d_in[0];
    const float* xc      = (const float*)d_in[1];
    const float* fc_W1   = (const float*)d_in[2];
    const float* fc_b1   = (const float*)d_in[3];
    const float* fc_W2   = (const float*)d_in[4];
    const float* fc_b2   = (const float*)d_in[5];
    const float* fcR_W1  = (const float*)d_in[6];
    const float* fcR_b1  = (const float*)d_in[7];
    const float* fcR_W2  = (const float*)d_in[8];
    const float* fcR_b2  = (const float*)d_in[9];
    const float* fcT1_W1 = (const float*)d_in[10];
    const float* fcT1_b1 = (const float*)d_in[11];
    const float* fcT1_W2 = (const float*)d_in[12];
    const float* fcT1_b2 = (const float*)d_in[13];
    const float* fcT2_W1 = (const float*)d_in[14];
    const float* fcT2_b1 = (const float*)d_in[15];
    const float* fcT2_W2 = (const float*)d_in[16];
    const float* fcT2_b2 = (const float*)d_in[17];

    cudaFuncSetAttribute(mlp_kernel, cudaFuncAttributeMaxDynamicSharedMemorySize,
                         SMEM_MLP_BYTES);

    prep_kernel<<<NSS, 256>>>(xc, fc_W1, fc_b1, fc_W2, fc_b2,
                              fcR_W1, fcR_b1, fcR_W2, fcR_b2,
                              fcT1_W1, fcT1_b1, fcT2_W1, fcT2_b1);

    pack_kernel<<<1, 256>>>(fcT1_W1, fcT2_W1, fcT1_W2, fcT1_b2, fcT2_W2, fcT2_b2);

    dim3 gB((NTT + 31)/32, NSS/8);
    mlp_kernel<<<gB, 256, SMEM_MLP_BYTES>>>(x);

    scan_kernel<<<(NSH + 127)/128, 128>>>();

    conv_kernel<<<NSS, CVT>>>((float*)d_out);
}

// round 9
// speedup vs baseline: 1.6993x; 1.1828x over previous
#include <cuda_runtime.h>
#include <math.h>
#include <stdint.h>

#define NTT 730
#define NSS 2000
#define NHH 16
#define NRR 15
#define NSH (NSS*NHH)          // 32000
#define NTS (NTT*NSS)          // 1460000

#define L2E2 2.8853900817779268f   // 2*log2(e)
#define W2S 132                    // float2 row stride: 132 mod 16 == 4 -> conflict-free

// -------- scratch (device globals; no allocation) --------
__device__ __align__(128) float  g_b1T[NSS*256];     // [s][k]
__device__ __align__(128) float  g_b2T[NSS*256];
__device__ __align__(128) float4 g_wc4[256];         // first-layer x-coeffs
__device__ __align__(128) float2 g_W2T[48*W2S];      // tf32 pairs, [o][j*4+c]
__device__ __align__(128) float  g_sbias[48];
__device__ __align__(128) float g_k1[NSH], g_k2[NSH], g_k23[NSH], g_k3[NSH];
__device__ __align__(128) float g_gl[NSH], g_qb[NSH], g_ge1[NSH], g_ge2[NSH];
__device__ __align__(128) float g_cw[NSH*NRR];
__device__ __align__(128) float g_vi[(size_t)NTT*NSH];
__device__ __align__(128) float g_vk[(size_t)NTT*NSH];
__device__ __align__(128) float g_vm[(size_t)NTT*NSH];
__device__ __align__(128) float g_Ps[NTS], g_Pl[NTS], g_E[NTS];
__device__ __align__(128) float g_QT[(size_t)NTT*NSH];

__device__ __forceinline__ float tanh_fast(float x) {
    float e = __expf(2.f * x);
    return 1.f - __fdividef(2.f, e + 1.f);
}
__device__ __forceinline__ float sigmoid_f(float x) {
    return __fdividef(1.f, 1.f + __expf(-x));
}
__device__ __forceinline__ float hsig(float x) {
    return __saturatef(x * (1.f/6.f) + 0.5f);
}
__device__ __forceinline__ float tanhaf(float x) {
    float r; asm("tanh.approx.f32 %0, %1;" : "=f"(r) : "f"(x));
    return r;
}
__device__ __forceinline__ float ex2f(float t) {
    float e; asm("ex2.approx.f32 %0, %1;" : "=f"(e) : "f"(t));
    return e;
}
__device__ __forceinline__ uint32_t cvt_tf32(float x) {
    uint32_t r; asm("cvt.rna.tf32.f32 %0, %1;" : "=r"(r) : "f"(x));
    return r;
}
__device__ __forceinline__ void mma8(float* d, const uint32_t* a, float2 b) {
    uint32_t b0 = __float_as_uint(b.x), b1 = __float_as_uint(b.y);
    asm("mma.sync.aligned.m16n8k8.row.col.f32.tf32.tf32.f32 "
        "{%0,%1,%2,%3}, {%4,%5,%6,%7}, {%8,%9}, {%0,%1,%2,%3};"
        : "+f"(d[0]), "+f"(d[1]), "+f"(d[2]), "+f"(d[3])
        : "r"(a[0]), "r"(a[1]), "r"(a[2]), "r"(a[3]), "r"(b0), "r"(b1));
}

// =====================================================================
// Kernel A: per-basin MLPs (w, wR) + transposed bases
// =====================================================================
__global__ __launch_bounds__(256) void prep_kernel(
    const float* __restrict__ xc,
    const float* __restrict__ fc_W1,  const float* __restrict__ fc_b1,
    const float* __restrict__ fc_W2,  const float* __restrict__ fc_b2,
    const float* __restrict__ fcR_W1, const float* __restrict__ fcR_b1,
    const float* __restrict__ fcR_W2, const float* __restrict__ fcR_b2,
    const float* __restrict__ fcT1_W1,const float* __restrict__ fcT1_b1,
    const float* __restrict__ fcT2_W1,const float* __restrict__ fcT2_b1)
{
    int s = blockIdx.x;
    int tid = threadIdx.x;
    __shared__ float sxc[32];
    __shared__ float sh_h[256], sh_hR[256];
    __shared__ float sh_w[160], sh_wR[240];
    __shared__ float sh_ga[16];

    if (tid < 32) sxc[tid] = xc[s*32 + tid];
    __syncthreads();

    {
        int k = tid;
        float a0 = fc_b1[k], a1 = fcR_b1[k], a2 = fcT1_b1[k], a3 = fcT2_b1[k];
        #pragma unroll
        for (int g = 0; g < 32; g++) {
            float xg = sxc[g];
            a0 += xg * fc_W1 [k*32 + g];
            a1 += xg * fcR_W1[k*32 + g];
            a2 += xg * fcT1_W1[k*33 + 1 + g];
            a3 += xg * fcT2_W1[k*35 + 3 + g];
        }
        sh_h[k]  = tanh_fast(a0);
        sh_hR[k] = tanh_fast(a1);
        g_b1T[s*256 + k] = a2;
        g_b2T[s*256 + k] = a3;
    }
    __syncthreads();

    int warp = tid >> 5, lane = tid & 31;
    for (int o = warp; o < 400; o += 8) {
        float sum = 0.f;
        if (o < 160) {
            const float* w = fc_W2 + o*256;
            for (int k = lane; k < 256; k += 32) sum += sh_h[k] * w[k];
        } else {
            const float* w = fcR_W2 + (o-160)*256;
            for (int k = lane; k < 256; k += 32) sum += sh_hR[k] * w[k];
        }
        #pragma unroll
        for (int off = 16; off; off >>= 1) sum += __shfl_down_sync(0xffffffffu, sum, off);
        if (lane == 0) {
            if (o < 160) sh_w[o] = sum + fc_b2[o];
            else         sh_wR[o-160] = sum + fcR_b2[o-160];
        }
    }
    __syncthreads();

    if (tid < 16) {
        int h = tid, g = s*16 + h;
        g_k1 [g] = sigmoid_f(sh_w[ 16 + h]);
        g_k2 [g] = sigmoid_f(sh_w[ 32 + h]);
        g_k23[g] = sigmoid_f(sh_w[ 48 + h]);
        g_k3 [g] = sigmoid_f(sh_w[ 64 + h]) * 0.1f;
        g_gl [g] = __expf(sh_w[ 80 + h]) * 2.f;
        g_qb [g] = fmaxf(sh_w[112 + h], 0.f);
        g_ge1[g] = fmaxf(sh_w[128 + h], 0.f);
        g_ge2[g] = fmaxf(sh_w[144 + h], 0.f);
        float m = -1e30f;
        #pragma unroll
        for (int j = 0; j < 16; j++) m = fmaxf(m, sh_w[96 + j]);
        float den = 0.f;
        #pragma unroll
        for (int j = 0; j < 16; j++) den += __expf(sh_w[96 + j] - m);
        sh_ga[h] = __fdividef(__expf(sh_w[96 + h] - m), den);
    }
    __syncthreads();

    if (tid < 240) {
        int h = tid / 15, d = tid - h*15;
        g_cw[(s*16 + h)*15 + d] = sh_ga[h] * fmaxf(sh_wR[h*15 + (14 - d)], 0.f);
    }
}

// =====================================================================
// Kernel A2: pack W2 into [o][j*4+c] tf32 pairs + wc/bias tables
// =====================================================================
__global__ __launch_bounds__(256) void pack_kernel(
    const float* __restrict__ fcT1_W1, const float* __restrict__ fcT2_W1,
    const float* __restrict__ fcT1_W2, const float* __restrict__ fcT1_b2,
    const float* __restrict__ fcT2_W2, const float* __restrict__ fcT2_b2)
{
    int tid = threadIdx.x;
    {
        int k = tid;
        g_wc4[k] = make_float4(fcT1_W1[k*33],
                               fcT2_W1[k*35],
                               fcT2_W1[k*35 + 1],
                               fcT2_W1[k*35 + 2]);
    }
    if (tid < 48) g_sbias[tid] = (tid < 32) ? fcT1_b2[tid] : fcT2_b2[tid - 32];

    for (int idx = tid; idx < 48*W2S; idx += 256) {
        int o = idx / W2S, km = idx - o*W2S;
        float2 v = make_float2(0.f, 0.f);
        if (km < 128) {
            int j = km >> 2, c = km & 3;
            int k0 = 8*j + c, k1 = k0 + 4;
            float w0 = (o < 32) ? fcT1_W2[o*256 + k0] : fcT2_W2[(o-32)*256 + k0];
            float w1 = (o < 32) ? fcT1_W2[o*256 + k1] : fcT2_W2[(o-32)*256 + k1];
            v = make_float2(__uint_as_float(cvt_tf32(w0)), __uint_as_float(cvt_tf32(w1)));
        }
        g_W2T[idx] = v;
    }
}

// =====================================================================
// Kernel B: tensor-core MLP. warp = 32 timesteps x 1 basin (2 mma tiles).
// =====================================================================
#define SMEM_MLP_BYTES (48*W2S*8 + 256*16 + 8*256*8 + 48*4)   // 71360

__global__ __launch_bounds__(256, 2) void mlp_kernel(const float* __restrict__ x)
{
    extern __shared__ float smem[];
    float2* sW2T  = (float2*)smem;                          // [48*W2S]
    float4* swc   = (float4*)(smem + 48*W2S*2);             // [256]
    float2* sb12  = (float2*)(swc + 256);                   // [8][256] {b1,b2}
    float*  sbias = (float*)(sb12 + 8*256);                 // [48]

    int tid = threadIdx.x;
    int w = tid >> 5, lane = tid & 31;
    int c = lane & 3, r = lane >> 2;

    {
        const uint4* src = (const uint4*)g_W2T;
        uint4* dst = (uint4*)sW2T;
        for (int i = tid; i < 48*W2S/2; i += 256) dst[i] = src[i];
        swc[tid] = g_wc4[tid];
        if (tid < 48) sbias[tid] = g_sbias[tid];
    }
    int s = blockIdx.y*8 + w;
    {
        const float* b1s = g_b1T + s*256;
        const float* b2s = g_b2T + s*256;
        float2* sb = sb12 + w*256;
        for (int k = lane; k < 256; k += 32)
            sb[k] = make_float2(b1s[k], b2s[k]);
    }
    __syncthreads();

    int t0 = blockIdx.x * 32;
    int tA = t0 + r;
    int tB = tA + 8;
    int tC = tA + 16;
    int tD = tA + 24;             // may overflow on last tile
    bool vD = (tD < NTT);
    int tDl = vD ? tD : (NTT-1);

    const float* xA = x + (size_t)(tA *NSS + s)*6;
    const float* xB = x + (size_t)(tB *NSS + s)*6;
    const float* xC = x + (size_t)(tC *NSS + s)*6;
    const float* xD = x + (size_t)(tDl*NSS + s)*6;
    float PA = xA[0], EA = xA[1], T1A = xA[2], T2A = xA[3], RA = xA[4], LA = xA[5];
    float PB = xB[0], EB = xB[1], T1B = xB[2], T2B = xB[3], RB = xB[4], LB = xB[5];
    float PC = xC[0], EC = xC[1], T1C = xC[2], T2C = xC[3], RC = xC[4], LC = xC[5];
    float PD = xD[0], ED = xD[1], T1D = xD[2], T2D = xD[3], RD = xD[4], LD = xD[5];

    if (c == 0) {
        #pragma unroll
        for (int q = 0; q < 4; q++) {
            float P  = (q==0)?PA :(q==1)?PB :(q==2)?PC :PD;
            float E  = (q==0)?EA :(q==1)?EB :(q==2)?EC :ED;
            float T1 = (q==0)?T1A:(q==1)?T1B:(q==2)?T1C:T1D;
            float T2 = (q==0)?T2A:(q==1)?T2B:(q==2)?T2C:T2D;
            int   t  = (q==0)?tA :(q==1)?tB :(q==2)?tC :tD;
            if (q == 3 && !vD) break;
            float dn = T2 - T1;
            float rr = (T1 + T2) / (dn == 0.f ? 1.f : dn);
            rr = fminf(fmaxf(rr, -1.f), 1.f);
            if ((T1 >= 0.f) || (T2 <= 0.f)) rr = 0.f;
            float vp = 1.f - acosf(rr) / 3.1415f;
            if (T1 >= 0.f) vp = 1.f;
            if (T2 <= 0.f) vp = 0.f;
            int ts = t*NSS + s;
            g_Ps[ts] = P * (1.f - vp);
            g_Pl[ts] = P * vp;
            g_E[ts]  = E;
        }
    }

    float dAB[6][4], dCD[6][4];
    #pragma unroll
    for (int g = 0; g < 6; g++)
        #pragma unroll
        for (int i = 0; i < 4; i++) { dAB[g][i] = 0.f; dCD[g][i] = 0.f; }

    const float2* sb = sb12 + w*256;

    #pragma unroll 2
    for (int j = 0; j < 32; j++) {
        int k0 = j*8 + c;
        float2 b0 = sb[k0];
        float2 b4 = sb[k0 + 4];
        float4 w0 = swc[k0], w1 = swc[k0+4];

        uint32_t aa1AB[4], aa1CD[4], aa2AB[4], aa2CD[4];
        aa1AB[0] = cvt_tf32(tanhaf(fmaf(LA, w0.x, b0.x)));
        aa1AB[1] = cvt_tf32(tanhaf(fmaf(LB, w0.x, b0.x)));
        aa1AB[2] = cvt_tf32(tanhaf(fmaf(LA, w1.x, b4.x)));
        aa1AB[3] = cvt_tf32(tanhaf(fmaf(LB, w1.x, b4.x)));
        aa1CD[0] = cvt_tf32(tanhaf(fmaf(LC, w0.x, b0.x)));
        aa1CD[1] = cvt_tf32(tanhaf(fmaf(LD, w0.x, b0.x)));
        aa1CD[2] = cvt_tf32(tanhaf(fmaf(LC, w1.x, b4.x)));
        aa1CD[3] = cvt_tf32(tanhaf(fmaf(LD, w1.x, b4.x)));
        aa2AB[0] = cvt_tf32(tanhaf(fmaf(RA, w0.y, fmaf(T1A, w0.z, fmaf(T2A, w0.w, b0.y)))));
        aa2AB[1] = cvt_tf32(tanhaf(fmaf(RB, w0.y, fmaf(T1B, w0.z, fmaf(T2B, w0.w, b0.y)))));
        aa2AB[2] = cvt_tf32(tanhaf(fmaf(RA, w1.y, fmaf(T1A, w1.z, fmaf(T2A, w1.w, b4.y)))));
        aa2AB[3] = cvt_tf32(tanhaf(fmaf(RB, w1.y, fmaf(T1B, w1.z, fmaf(T2B, w1.w, b4.y)))));
        aa2CD[0] = cvt_tf32(tanhaf(fmaf(RC, w0.y, fmaf(T1C, w0.z, fmaf(T2C, w0.w, b0.y)))));
        aa2CD[1] = cvt_tf32(tanhaf(fmaf(RD, w0.y, fmaf(T1D, w0.z, fmaf(T2D, w0.w, b0.y)))));
        aa2CD[2] = cvt_tf32(tanhaf(fmaf(RC, w1.y, fmaf(T1C, w1.z, fmaf(T2C, w1.w, b4.y)))));
        aa2CD[3] = cvt_tf32(tanhaf(fmaf(RD, w1.y, fmaf(T1D, w1.z, fmaf(T2D, w1.w, b4.y)))));

        const float2* Wb = sW2T + (j*4 + c);
        #pragma unroll
        for (int g = 0; g < 4; g++) {
            float2 bw = Wb[(8*g + r)*W2S];
            mma8(dAB[g], aa1AB, bw);
            mma8(dCD[g], aa1CD, bw);
        }
        #pragma unroll
        for (int g = 4; g < 6; g++) {
            float2 bw = Wb[(8*g + r)*W2S];
            mma8(dAB[g], aa2AB, bw);
            mma8(dCD[g], aa2CD, bw);
        }
    }

    #pragma unroll
    for (int g = 0; g < 6; g++) {
        int o = 8*g + 2*c;
        float bi0 = sbias[o], bi1 = sbias[o+1];
        float2 oA, oB, oC, oD;
        float* arr;
        if (g < 4) {
            oA = make_float2(hsig(dAB[g][0]+bi0), hsig(dAB[g][1]+bi1));
            oB = make_float2(hsig(dAB[g][2]+bi0), hsig(dAB[g][3]+bi1));
            oC = make_float2(hsig(dCD[g][0]+bi0), hsig(dCD[g][1]+bi1));
            oD = make_float2(hsig(dCD[g][2]+bi0), hsig(dCD[g][3]+bi1));
            arr = (g < 2) ? g_vi : g_vk;
        } else {
            oA = make_float2(ex2f((dAB[g][0]+bi0)*L2E2), ex2f((dAB[g][1]+bi1)*L2E2));
            oB = make_float2(ex2f((dAB[g][2]+bi0)*L2E2), ex2f((dAB[g][3]+bi1)*L2E2));
            oC = make_float2(ex2f((dCD[g][0]+bi0)*L2E2), ex2f((dCD[g][1]+bi1)*L2E2));
            oD = make_float2(ex2f((dCD[g][2]+bi0)*L2E2), ex2f((dCD[g][3]+bi1)*L2E2));
            arr = g_vm;
        }
        int h = o & 15;
        size_t off = (size_t)s*16 + h;
        *(float2*)(arr + (size_t)tA*NSH + off) = oA;
        *(float2*)(arr + (size_t)tB*NSH + off) = oB;
        *(float2*)(arr + (size_t)tC*NSH + off) = oC;
        if (vD) *(float2*)(arr + (size_t)tD*NSH + off) = oD;
    }
}

// =====================================================================
// Kernel C: sequential reservoir scan; thread = (s,h).
// Prefetch distance 8 with STATIC slots: outer loop steps 8, inner
// fully unrolled, slot = u (compile-time). Scalar streams for max MLP.
// =====================================================================
#define SCP 8
__global__ __launch_bounds__(128) void scan_kernel()
{
    int g = blockIdx.x * 128 + threadIdx.x;
    if (g >= NSH) return;
    int s = g >> 4;
    float k1 = g_k1[g], k2 = g_k2[g], k23 = g_k23[g], k3 = g_k3[g];
    float gl = g_gl[g], qb = g_qb[g], ge1 = g_ge1[g], ge2 = g_ge2[g];
    float S0 = 0.f, Sv = 0.f, S2 = 0.f, S3 = 0.f;

    float b_vi[SCP], b_vk[SCP], b_vm[SCP], b_Ps[SCP], b_Pl[SCP], b_E[SCP];
    #pragma unroll
    for (int i = 0; i < SCP; i++) {
        size_t tg = (size_t)i*NSH + g;
        int ts = i*NSS + s;
        b_vi[i] = __ldg(g_vi + tg);
        b_vk[i] = __ldg(g_vk + tg);
        b_vm[i] = __ldg(g_vm + tg);
        b_Ps[i] = __ldg(g_Ps + ts);
        b_Pl[i] = __ldg(g_Pl + ts);
        b_E [i] = __ldg(g_E  + ts);
    }

    for (int tb = 0; tb < NTT; tb += SCP) {
        #pragma unroll
        for (int u = 0; u < SCP; u++) {
            int t = tb + u;
            if (t >= NTT) break;

            float Ps = b_Ps[u], Pl = b_Pl[u], E = b_E[u];
            float vi = b_vi[u], vk = b_vk[u], vm = b_vm[u];

            int tn = t + SCP;
            if (tn < NTT) {
                size_t tg = (size_t)tn*NSH + g;
                int ts = tn*NSS + s;
                b_vi[u] = __ldg(g_vi + tg);
                b_vk[u] = __ldg(g_vk + tg);
                b_vm[u] = __ldg(g_vm + tg);
                b_Ps[u] = __ldg(g_Ps + ts);
                b_Pl[u] = __ldg(g_Pl + ts);
                b_E [u] = __ldg(g_E  + ts);
            }

            float H0  = S0 + Ps;
            float qSm = fminf(H0, vm);
            float Hv  = fmaxf(Sv + Pl*(1.f - vi) - E*ge1, 0.f);
            float qv  = Sv * vk;
            float H2  = fmaxf(S2 + qSm + qv - E*ge2 + Pl*vi, 0.f);
            float x1  = H2 - gl;
            float Q1  = (x1 > 0.f) ? exp2f(k1 * __log2f(x1)) : 0.f;
            float q2  = fminf(H2, gl) * k2;
            float Q2  = q2 * (1.f - k23);
            float H3  = S3 + q2 * k23;
            float Q3  = H3 * k3 + qb;

            S0 = H0 - qSm;
            Sv = Hv - qv;
            S2 = H2 - Q1 - q2;
            S3 = H3 - Q3;
            g_QT[(size_t)t*NSH + g] = Q1 + Q2 + Q3;
        }
    }
}

// =====================================================================
// Kernel D: causal depthwise conv + head-sum, register-blocked 4 t/thread
// =====================================================================
#define CVT 192
#define CVS 788
__global__ __launch_bounds__(CVT) void conv_kernel(float* __restrict__ out)
{
    __shared__ float shQ[16*CVS];
    __shared__ float shc[NHH*NRR];
    int s = blockIdx.x;
    int tid = threadIdx.x;

    for (int i = tid; i < 16*CVS; i += CVT) {
        int j = i >> 4, h = i & 15;
        int t = j - 14;
        shQ[h*CVS + j] = (t >= 0 && t < NTT)
            ? g_QT[(size_t)t*NSH + s*16 + h] : 0.f;
    }
    for (int i = tid; i < 240; i += CVT) shc[i] = g_cw[s*240 + i];
    __syncthreads();

    int tb = tid * 4;
    if (tb < NTT) {
        float acc0 = 0.f, acc1 = 0.f, acc2 = 0.f, acc3 = 0.f;
        #pragma unroll
        for (int h = 0; h < 16; h++) {
            const float4* qw = (const float4*)(shQ + h*CVS + tb);
            float wv[20];
            #pragma unroll
            for (int v = 0; v < 5; v++) {
                float4 q4 = qw[v];
                wv[4*v+0] = q4.x; wv[4*v+1] = q4.y; wv[4*v+2] = q4.z; wv[4*v+3] = q4.w;
            }
            #pragma unroll
            for (int d = 0; d < 15; d++) {
                float cc = shc[h*15 + d];
                acc0 += wv[14 - d] * cc;
                acc1 += wv[15 - d] * cc;
                acc2 += wv[16 - d] * cc;
                acc3 += wv[17 - d] * cc;
            }
        }
        out[(tb+0)*NSS + s] = acc0;
        if (tb+1 < NTT) out[(tb+1)*NSS + s] = acc1;
        if (tb+2 < NTT) out[(tb+2)*NSS + s] = acc2;
        if (tb+3 < NTT) out[(tb+3)*NSS + s] = acc3;
    }
}

// =====================================================================
extern "C" void kernel_launch(void* const* d_in, const int* in_sizes, int n_in,
                              void* d_out, int out_size)
{
    const float* x       = (const float*)d_in[0];
    const float* xc      = (const float*)d_in[1];
    const float* fc_W1   = (const float*)d_in[2];
    const float* fc_b1   = (const float*)d_in[3];
    const float* fc_W2   = (const float*)d_in[4];
    const float* fc_b2   = (const float*)d_in[5];
    const float* fcR_W1  = (const float*)d_in[6];
    const float* fcR_b1  = (const float*)d_in[7];
    const float* fcR_W2  = (const float*)d_in[8];
    const float* fcR_b2  = (const float*)d_in[9];
    const float* fcT1_W1 = (const float*)d_in[10];
    const float* fcT1_b1 = (const float*)d_in[11];
    const float* fcT1_W2 = (const float*)d_in[12];
    const float* fcT1_b2 = (const float*)d_in[13];
    const float* fcT2_W1 = (const float*)d_in[14];
    const float* fcT2_b1 = (const float*)d_in[15];
    const float* fcT2_W2 = (const float*)d_in[16];
    const float* fcT2_b2 = (const float*)d_in[17];

    cudaFuncSetAttribute(mlp_kernel, cudaFuncAttributeMaxDynamicSharedMemorySize,
                         SMEM_MLP_BYTES);

    prep_kernel<<<NSS, 256>>>(xc, fc_W1, fc_b1, fc_W2, fc_b2,
                              fcR_W1, fcR_b1, fcR_W2, fcR_b2,
                              fcT1_W1, fcT1_b1, fcT2_W1, fcT2_b1);

    pack_kernel<<<1, 256>>>(fcT1_W1, fcT2_W1, fcT1_W2, fcT1_b2, fcT2_W2, fcT2_b2);

    dim3 gB((NTT + 31)/32, NSS/8);
    mlp_kernel<<<gB, 256, SMEM_MLP_BYTES>>>(x);

    scan_kernel<<<(NSH + 127)/128, 128>>>();

    conv_kernel<<<NSS, CVT>>>((float*)d_out);
}

// round 10
// speedup vs baseline: 1.7892x; 1.0529x over previous
#include <cuda_runtime.h>
#include <cuda_fp16.h>
#include <math.h>
#include <stdint.h>

#define NTT 730
#define NSS 2000
#define NHH 16
#define NRR 15
#define NSH (NSS*NHH)          // 32000
#define NTS (NTT*NSS)          // 1460000

#define L2E2 2.8853900817779268f   // 2*log2(e)
#define W2S 132                    // uint32 row stride: bank = lane + 8j (perfect perm)

// -------- scratch (device globals; no allocation) --------
__device__ __align__(128) float    g_b1T[NSS*256];   // [s][k]
__device__ __align__(128) float    g_b2T[NSS*256];
__device__ __align__(128) float4   g_wc4[256];       // first-layer x-coeffs
__device__ __align__(128) uint32_t g_W2h[48*W2S];    // half2 pairs (2p, 2p+1), [o][p]
__device__ __align__(128) float    g_sbias[48];
__device__ __align__(128) float g_k1[NSH], g_k2[NSH], g_k23[NSH], g_k3[NSH];
__device__ __align__(128) float g_gl[NSH], g_qb[NSH], g_ge1[NSH], g_ge2[NSH];
__device__ __align__(128) float g_cw[NSH*NRR];
__device__ __align__(128) float g_vi[(size_t)NTT*NSH];
__device__ __align__(128) float g_vk[(size_t)NTT*NSH];
__device__ __align__(128) float g_vm[(size_t)NTT*NSH];
__device__ __align__(128) float g_Ps[NTS], g_Pl[NTS], g_E[NTS];
__device__ __align__(128) float g_QT[(size_t)NTT*NSH];

__device__ __forceinline__ float tanh_fast(float x) {
    float e = __expf(2.f * x);
    return 1.f - __fdividef(2.f, e + 1.f);
}
__device__ __forceinline__ float sigmoid_f(float x) {
    return __fdividef(1.f, 1.f + __expf(-x));
}
__device__ __forceinline__ float hsig(float x) {
    return __saturatef(x * (1.f/6.f) + 0.5f);
}
__device__ __forceinline__ float tanhaf(float x) {
    float r; asm("tanh.approx.f32 %0, %1;" : "=f"(r) : "f"(x));
    return r;
}
__device__ __forceinline__ float ex2f(float t) {
    float e; asm("ex2.approx.f32 %0, %1;" : "=f"(e) : "f"(t));
    return e;
}
__device__ __forceinline__ uint32_t packh2(float lo, float hi) {
    __half2 h = __floats2half2_rn(lo, hi);     // x = lo half
    return *reinterpret_cast<uint32_t*>(&h);
}
__device__ __forceinline__ void mma16(float* d, const uint32_t* a,
                                      uint32_t b0, uint32_t b1) {
    asm("mma.sync.aligned.m16n8k16.row.col.f32.f16.f16.f32 "
        "{%0,%1,%2,%3}, {%4,%5,%6,%7}, {%8,%9}, {%0,%1,%2,%3};"
        : "+f"(d[0]), "+f"(d[1]), "+f"(d[2]), "+f"(d[3])
        : "r"(a[0]), "r"(a[1]), "r"(a[2]), "r"(a[3]), "r"(b0), "r"(b1));
}

// =====================================================================
// Kernel A: per-basin MLPs (w, wR) + transposed bases
// =====================================================================
__global__ __launch_bounds__(256) void prep_kernel(
    const float* __restrict__ xc,
    const float* __restrict__ fc_W1,  const float* __restrict__ fc_b1,
    const float* __restrict__ fc_W2,  const float* __restrict__ fc_b2,
    const float* __restrict__ fcR_W1, const float* __restrict__ fcR_b1,
    const float* __restrict__ fcR_W2, const float* __restrict__ fcR_b2,
    const float* __restrict__ fcT1_W1,const float* __restrict__ fcT1_b1,
    const float* __restrict__ fcT2_W1,const float* __restrict__ fcT2_b1)
{
    int s = blockIdx.x;
    int tid = threadIdx.x;
    __shared__ float sxc[32];
    __shared__ float sh_h[256], sh_hR[256];
    __shared__ float sh_w[160], sh_wR[240];
    __shared__ float sh_ga[16];

    if (tid < 32) sxc[tid] = xc[s*32 + tid];
    __syncthreads();

    {
        int k = tid;
        float a0 = fc_b1[k], a1 = fcR_b1[k], a2 = fcT1_b1[k], a3 = fcT2_b1[k];
        #pragma unroll
        for (int g = 0; g < 32; g++) {
            float xg = sxc[g];
            a0 += xg * fc_W1 [k*32 + g];
            a1 += xg * fcR_W1[k*32 + g];
            a2 += xg * fcT1_W1[k*33 + 1 + g];
            a3 += xg * fcT2_W1[k*35 + 3 + g];
        }
        sh_h[k]  = tanh_fast(a0);
        sh_hR[k] = tanh_fast(a1);
        g_b1T[s*256 + k] = a2;
        g_b2T[s*256 + k] = a3;
    }
    __syncthreads();

    int warp = tid >> 5, lane = tid & 31;
    for (int o = warp; o < 400; o += 8) {
        float sum = 0.f;
        if (o < 160) {
            const float* w = fc_W2 + o*256;
            for (int k = lane; k < 256; k += 32) sum += sh_h[k] * w[k];
        } else {
            const float* w = fcR_W2 + (o-160)*256;
            for (int k = lane; k < 256; k += 32) sum += sh_hR[k] * w[k];
        }
        #pragma unroll
        for (int off = 16; off; off >>= 1) sum += __shfl_down_sync(0xffffffffu, sum, off);
        if (lane == 0) {
            if (o < 160) sh_w[o] = sum + fc_b2[o];
            else         sh_wR[o-160] = sum + fcR_b2[o-160];
        }
    }
    __syncthreads();

    if (tid < 16) {
        int h = tid, g = s*16 + h;
        g_k1 [g] = sigmoid_f(sh_w[ 16 + h]);
        g_k2 [g] = sigmoid_f(sh_w[ 32 + h]);
        g_k23[g] = sigmoid_f(sh_w[ 48 + h]);
        g_k3 [g] = sigmoid_f(sh_w[ 64 + h]) * 0.1f;
        g_gl [g] = __expf(sh_w[ 80 + h]) * 2.f;
        g_qb [g] = fmaxf(sh_w[112 + h], 0.f);
        g_ge1[g] = fmaxf(sh_w[128 + h], 0.f);
        g_ge2[g] = fmaxf(sh_w[144 + h], 0.f);
        float m = -1e30f;
        #pragma unroll
        for (int j = 0; j < 16; j++) m = fmaxf(m, sh_w[96 + j]);
        float den = 0.f;
        #pragma unroll
        for (int j = 0; j < 16; j++) den += __expf(sh_w[96 + j] - m);
        sh_ga[h] = __fdividef(__expf(sh_w[96 + h] - m), den);
    }
    __syncthreads();

    if (tid < 240) {
        int h = tid / 15, d = tid - h*15;
        g_cw[(s*16 + h)*15 + d] = sh_ga[h] * fmaxf(sh_wR[h*15 + (14 - d)], 0.f);
    }
}

// =====================================================================
// Kernel A2: pack W2 into half2 (2p, 2p+1) pairs [o][p] + wc/bias tables
// =====================================================================
__global__ __launch_bounds__(256) void pack_kernel(
    const float* __restrict__ fcT1_W1, const float* __restrict__ fcT2_W1,
    const float* __restrict__ fcT1_W2, const float* __restrict__ fcT1_b2,
    const float* __restrict__ fcT2_W2, const float* __restrict__ fcT2_b2)
{
    int tid = threadIdx.x;
    {
        int k = tid;
        g_wc4[k] = make_float4(fcT1_W1[k*33],
                               fcT2_W1[k*35],
                               fcT2_W1[k*35 + 1],
                               fcT2_W1[k*35 + 2]);
    }
    if (tid < 48) g_sbias[tid] = (tid < 32) ? fcT1_b2[tid] : fcT2_b2[tid - 32];

    for (int idx = tid; idx < 48*W2S; idx += 256) {
        int o = idx / W2S, p = idx - o*W2S;
        uint32_t v = 0;
        if (p < 128) {
            int k0 = 2*p, k1 = 2*p + 1;
            float w0 = (o < 32) ? fcT1_W2[o*256 + k0] : fcT2_W2[(o-32)*256 + k0];
            float w1 = (o < 32) ? fcT1_W2[o*256 + k1] : fcT2_W2[(o-32)*256 + k1];
            v = packh2(w0, w1);
        }
        g_W2h[idx] = v;
    }
}

// =====================================================================
// Kernel B: fp16 tensor-core MLP (m16n8k16). warp = 32 timesteps x 1 basin.
// =====================================================================
#define SMEM_MLP_F (48*W2S + 256*4 + 8*256*2 + 48)   // 11504 floats
#define SMEM_MLP_BYTES (SMEM_MLP_F*4)                // 46016

__global__ __launch_bounds__(256, 2) void mlp_kernel(const float* __restrict__ x)
{
    extern __shared__ float smem[];
    uint32_t* sW2h  = (uint32_t*)smem;                 // [48*W2S]
    float4*   swc   = (float4*)(smem + 48*W2S);        // [256]
    float2*   sb12  = (float2*)(swc + 256);            // [8][256] {b1,b2}
    float*    sbias = (float*)(sb12 + 8*256);          // [48]

    int tid = threadIdx.x;
    int w = tid >> 5, lane = tid & 31;
    int c = lane & 3, r = lane >> 2;

    {
        const uint4* src = (const uint4*)g_W2h;
        uint4* dst = (uint4*)sW2h;
        for (int i = tid; i < 48*W2S/4; i += 256) dst[i] = src[i];
        swc[tid] = g_wc4[tid];
        if (tid < 48) sbias[tid] = g_sbias[tid];
    }
    int s = blockIdx.y*8 + w;
    {
        const float* b1s = g_b1T + s*256;
        const float* b2s = g_b2T + s*256;
        float2* sb = sb12 + w*256;
        for (int k = lane; k < 256; k += 32)
            sb[k] = make_float2(b1s[k], b2s[k]);
    }
    __syncthreads();

    int t0 = blockIdx.x * 32;
    int tA = t0 + r;
    int tB = tA + 8;
    int tC = tA + 16;
    int tD = tA + 24;             // may overflow on last tile
    bool vD = (tD < NTT);
    int tDl = vD ? tD : (NTT-1);

    const float* xA = x + (size_t)(tA *NSS + s)*6;
    const float* xB = x + (size_t)(tB *NSS + s)*6;
    const float* xC = x + (size_t)(tC *NSS + s)*6;
    const float* xD = x + (size_t)(tDl*NSS + s)*6;
    float PA = xA[0], EA = xA[1], T1A = xA[2], T2A = xA[3], RA = xA[4], LA = xA[5];
    float PB = xB[0], EB = xB[1], T1B = xB[2], T2B = xB[3], RB = xB[4], LB = xB[5];
    float PC = xC[0], EC = xC[1], T1C = xC[2], T2C = xC[3], RC = xC[4], LC = xC[5];
    float PD = xD[0], ED = xD[1], T1D = xD[2], T2D = xD[3], RD = xD[4], LD = xD[5];

    if (c == 0) {
        #pragma unroll
        for (int q = 0; q < 4; q++) {
            float P  = (q==0)?PA :(q==1)?PB :(q==2)?PC :PD;
            float E  = (q==0)?EA :(q==1)?EB :(q==2)?EC :ED;
            float T1 = (q==0)?T1A:(q==1)?T1B:(q==2)?T1C:T1D;
            float T2 = (q==0)?T2A:(q==1)?T2B:(q==2)?T2C:T2D;
            int   t  = (q==0)?tA :(q==1)?tB :(q==2)?tC :tD;
            if (q == 3 && !vD) break;
            float dn = T2 - T1;
            float rr = (T1 + T2) / (dn == 0.f ? 1.f : dn);
            rr = fminf(fmaxf(rr, -1.f), 1.f);
            if ((T1 >= 0.f) || (T2 <= 0.f)) rr = 0.f;
            float vp = 1.f - acosf(rr) / 3.1415f;
            if (T1 >= 0.f) vp = 1.f;
            if (T2 <= 0.f) vp = 0.f;
            int ts = t*NSS + s;
            g_Ps[ts] = P * (1.f - vp);
            g_Pl[ts] = P * vp;
            g_E[ts]  = E;
        }
    }

    float dAB[6][4], dCD[6][4];
    #pragma unroll
    for (int g = 0; g < 6; g++)
        #pragma unroll
        for (int i = 0; i < 4; i++) { dAB[g][i] = 0.f; dCD[g][i] = 0.f; }

    const float* sbf = (const float*)(sb12 + w*256);

    #define H2F(Rv,T1v,T2v,wc,b) tanhaf(fmaf(Rv, (wc).y, fmaf(T1v, (wc).z, fmaf(T2v, (wc).w, (b)))))

    #pragma unroll 1
    for (int j = 0; j < 16; j++) {
        int ka = 16*j + 2*c;        // even
        int kb = ka + 8;
        float4 bA = *(const float4*)(sbf + 2*ka);  // {b1[ka],b2[ka],b1[ka+1],b2[ka+1]}
        float4 bB = *(const float4*)(sbf + 2*kb);
        float4 wA0 = swc[ka], wA1 = swc[ka+1];
        float4 wB0 = swc[kb], wB1 = swc[kb+1];

        uint32_t a1AB[4], a1CD[4], a2AB[4], a2CD[4];
        a1AB[0] = packh2(tanhaf(fmaf(LA, wA0.x, bA.x)), tanhaf(fmaf(LA, wA1.x, bA.z)));
        a1AB[1] = packh2(tanhaf(fmaf(LB, wA0.x, bA.x)), tanhaf(fmaf(LB, wA1.x, bA.z)));
        a1AB[2] = packh2(tanhaf(fmaf(LA, wB0.x, bB.x)), tanhaf(fmaf(LA, wB1.x, bB.z)));
        a1AB[3] = packh2(tanhaf(fmaf(LB, wB0.x, bB.x)), tanhaf(fmaf(LB, wB1.x, bB.z)));
        a1CD[0] = packh2(tanhaf(fmaf(LC, wA0.x, bA.x)), tanhaf(fmaf(LC, wA1.x, bA.z)));
        a1CD[1] = packh2(tanhaf(fmaf(LD, wA0.x, bA.x)), tanhaf(fmaf(LD, wA1.x, bA.z)));
        a1CD[2] = packh2(tanhaf(fmaf(LC, wB0.x, bB.x)), tanhaf(fmaf(LC, wB1.x, bB.z)));
        a1CD[3] = packh2(tanhaf(fmaf(LD, wB0.x, bB.x)), tanhaf(fmaf(LD, wB1.x, bB.z)));

        a2AB[0] = packh2(H2F(RA,T1A,T2A,wA0,bA.y), H2F(RA,T1A,T2A,wA1,bA.w));
        a2AB[1] = packh2(H2F(RB,T1B,T2B,wA0,bA.y), H2F(RB,T1B,T2B,wA1,bA.w));
        a2AB[2] = packh2(H2F(RA,T1A,T2A,wB0,bB.y), H2F(RA,T1A,T2A,wB1,bB.w));
        a2AB[3] = packh2(H2F(RB,T1B,T2B,wB0,bB.y), H2F(RB,T1B,T2B,wB1,bB.w));
        a2CD[0] = packh2(H2F(RC,T1C,T2C,wA0,bA.y), H2F(RC,T1C,T2C,wA1,bA.w));
        a2CD[1] = packh2(H2F(RD,T1D,T2D,wA0,bA.y), H2F(RD,T1D,T2D,wA1,bA.w));
        a2CD[2] = packh2(H2F(RC,T1C,T2C,wB0,bB.y), H2F(RC,T1C,T2C,wB1,bB.w));
        a2CD[3] = packh2(H2F(RD,T1D,T2D,wB0,bB.y), H2F(RD,T1D,T2D,wB1,bB.w));

        const uint32_t* Wb = sW2h + 8*j + c;
        #pragma unroll
        for (int g = 0; g < 4; g++) {
            int ro = (8*g + r)*W2S;
            uint32_t b0 = Wb[ro], b1 = Wb[ro + 4];
            mma16(dAB[g], a1AB, b0, b1);
            mma16(dCD[g], a1CD, b0, b1);
        }
        #pragma unroll
        for (int g = 4; g < 6; g++) {
            int ro = (8*g + r)*W2S;
            uint32_t b0 = Wb[ro], b1 = Wb[ro + 4];
            mma16(dAB[g], a2AB, b0, b1);
            mma16(dCD[g], a2CD, b0, b1);
        }
    }
    #undef H2F

    #pragma unroll
    for (int g = 0; g < 6; g++) {
        int o = 8*g + 2*c;
        float bi0 = sbias[o], bi1 = sbias[o+1];
        float2 oA, oB, oC, oD;
        float* arr;
        if (g < 4) {
            oA = make_float2(hsig(dAB[g][0]+bi0), hsig(dAB[g][1]+bi1));
            oB = make_float2(hsig(dAB[g][2]+bi0), hsig(dAB[g][3]+bi1));
            oC = make_float2(hsig(dCD[g][0]+bi0), hsig(dCD[g][1]+bi1));
            oD = make_float2(hsig(dCD[g][2]+bi0), hsig(dCD[g][3]+bi1));
            arr = (g < 2) ? g_vi : g_vk;
        } else {
            oA = make_float2(ex2f((dAB[g][0]+bi0)*L2E2), ex2f((dAB[g][1]+bi1)*L2E2));
            oB = make_float2(ex2f((dAB[g][2]+bi0)*L2E2), ex2f((dAB[g][3]+bi1)*L2E2));
            oC = make_float2(ex2f((dCD[g][0]+bi0)*L2E2), ex2f((dCD[g][1]+bi1)*L2E2));
            oD = make_float2(ex2f((dCD[g][2]+bi0)*L2E2), ex2f((dCD[g][3]+bi1)*L2E2));
            arr = g_vm;
        }
        int h = o & 15;
        size_t off = (size_t)s*16 + h;
        *(float2*)(arr + (size_t)tA*NSH + off) = oA;
        *(float2*)(arr + (size_t)tB*NSH + off) = oB;
        *(float2*)(arr + (size_t)tC*NSH + off) = oC;
        if (vD) *(float2*)(arr + (size_t)tD*NSH + off) = oD;
    }
}

// =====================================================================
// Kernel C: sequential reservoir scan; thread = (s,h).
// Prefetch distance 16 with STATIC slots (outer step 16, inner unrolled).
// =====================================================================
#define SCP 16
__global__ __launch_bounds__(128) void scan_kernel()
{
    int g = blockIdx.x * 128 + threadIdx.x;
    if (g >= NSH) return;
    int s = g >> 4;
    float k1 = g_k1[g], k2 = g_k2[g], k23 = g_k23[g], k3 = g_k3[g];
    float gl = g_gl[g], qb = g_qb[g], ge1 = g_ge1[g], ge2 = g_ge2[g];
    float S0 = 0.f, Sv = 0.f, S2 = 0.f, S3 = 0.f;

    float b_vi[SCP], b_vk[SCP], b_vm[SCP], b_Ps[SCP], b_Pl[SCP], b_E[SCP];
    #pragma unroll
    for (int i = 0; i < SCP; i++) {
        size_t tg = (size_t)i*NSH + g;
        int ts = i*NSS + s;
        b_vi[i] = __ldg(g_vi + tg);
        b_vk[i] = __ldg(g_vk + tg);
        b_vm[i] = __ldg(g_vm + tg);
        b_Ps[i] = __ldg(g_Ps + ts);
        b_Pl[i] = __ldg(g_Pl + ts);
        b_E [i] = __ldg(g_E  + ts);
    }

    for (int tb = 0; tb < NTT; tb += SCP) {
        #pragma unroll
        for (int u = 0; u < SCP; u++) {
            int t = tb + u;
            if (t >= NTT) break;

            float Ps = b_Ps[u], Pl = b_Pl[u], E = b_E[u];
            float vi = b_vi[u], vk = b_vk[u], vm = b_vm[u];

            int tn = t + SCP;
            if (tn < NTT) {
                size_t tg = (size_t)tn*NSH + g;
                int ts = tn*NSS + s;
                b_vi[u] = __ldg(g_vi + tg);
                b_vk[u] = __ldg(g_vk + tg);
                b_vm[u] = __ldg(g_vm + tg);
                b_Ps[u] = __ldg(g_Ps + ts);
                b_Pl[u] = __ldg(g_Pl + ts);
                b_E [u] = __ldg(g_E  + ts);
            }

            float H0  = S0 + Ps;
            float qSm = fminf(H0, vm);
            float Hv  = fmaxf(Sv + Pl*(1.f - vi) - E*ge1, 0.f);
            float qv  = Sv * vk;
            float H2  = fmaxf(S2 + qSm + qv - E*ge2 + Pl*vi, 0.f);
            float x1  = H2 - gl;
            float Q1  = (x1 > 0.f) ? exp2f(k1 * __log2f(x1)) : 0.f;
            float q2  = fminf(H2, gl) * k2;
            float Q2  = q2 * (1.f - k23);
            float H3  = S3 + q2 * k23;
            float Q3  = H3 * k3 + qb;

            S0 = H0 - qSm;
            Sv = Hv - qv;
            S2 = H2 - Q1 - q2;
            S3 = H3 - Q3;
            g_QT[(size_t)t*NSH + g] = Q1 + Q2 + Q3;
        }
    }
}

// =====================================================================
// Kernel D: causal depthwise conv + head-sum, register-blocked 4 t/thread
// =====================================================================
#define CVT 192
#define CVS 788
__global__ __launch_bounds__(CVT) void conv_kernel(float* __restrict__ out)
{
    __shared__ float shQ[16*CVS];
    __shared__ float shc[NHH*NRR];
    int s = blockIdx.x;
    int tid = threadIdx.x;

    for (int i = tid; i < 16*CVS; i += CVT) {
        int j = i >> 4, h = i & 15;
        int t = j - 14;
        shQ[h*CVS + j] = (t >= 0 && t < NTT)
            ? g_QT[(size_t)t*NSH + s*16 + h] : 0.f;
    }
    for (int i = tid; i < 240; i += CVT) shc[i] = g_cw[s*240 + i];
    __syncthreads();

    int tb = tid * 4;
    if (tb < NTT) {
        float acc0 = 0.f, acc1 = 0.f, acc2 = 0.f, acc3 = 0.f;
        #pragma unroll
        for (int h = 0; h < 16; h++) {
            const float4* qw = (const float4*)(shQ + h*CVS + tb);
            float wv[20];
            #pragma unroll
            for (int v = 0; v < 5; v++) {
                float4 q4 = qw[v];
                wv[4*v+0] = q4.x; wv[4*v+1] = q4.y; wv[4*v+2] = q4.z; wv[4*v+3] = q4.w;
            }
            #pragma unroll
            for (int d = 0; d < 15; d++) {
                float cc = shc[h*15 + d];
                acc0 += wv[14 - d] * cc;
                acc1 += wv[15 - d] * cc;
                acc2 += wv[16 - d] * cc;
                acc3 += wv[17 - d] * cc;
            }
        }
        out[(tb+0)*NSS + s] = acc0;
        if (tb+1 < NTT) out[(tb+1)*NSS + s] = acc1;
        if (tb+2 < NTT) out[(tb+2)*NSS + s] = acc2;
        if (tb+3 < NTT) out[(tb+3)*NSS + s] = acc3;
    }
}

// =====================================================================
extern "C" void kernel_launch(void* const* d_in, const int* in_sizes, int n_in,
                              void* d_out, int out_size)
{
    const float* x       = (const float*)d_in[0];
    const float* xc      = (const float*)d_in[1];
    const float* fc_W1   = (const float*)d_in[2];
    const float* fc_b1   = (const float*)d_in[3];
    const float* fc_W2   = (const float*)d_in[4];
    const float* fc_b2   = (const float*)d_in[5];
    const float* fcR_W1  = (const float*)d_in[6];
    const float* fcR_b1  = (const float*)d_in[7];
    const float* fcR_W2  = (const float*)d_in[8];
    const float* fcR_b2  = (const float*)d_in[9];
    const float* fcT1_W1 = (const float*)d_in[10];
    const float* fcT1_b1 = (const float*)d_in[11];
    const float* fcT1_W2 = (const float*)d_in[12];
    const float* fcT1_b2 = (const float*)d_in[13];
    const float* fcT2_W1 = (const float*)d_in[14];
    const float* fcT2_b1 = (const float*)d_in[15];
    const float* fcT2_W2 = (const float*)d_in[16];
    const float* fcT2_b2 = (const float*)d_in[17];

    cudaFuncSetAttribute(mlp_kernel, cudaFuncAttributeMaxDynamicSharedMemorySize,
                         SMEM_MLP_BYTES);

    prep_kernel<<<NSS, 256>>>(xc, fc_W1, fc_b1, fc_W2, fc_b2,
                              fcR_W1, fcR_b1, fcR_W2, fcR_b2,
                              fcT1_W1, fcT1_b1, fcT2_W1, fcT2_b1);

    pack_kernel<<<1, 256>>>(fcT1_W1, fcT2_W1, fcT1_W2, fcT1_b2, fcT2_W2, fcT2_b2);

    dim3 gB((NTT + 31)/32, NSS/8);
    mlp_kernel<<<gB, 256, SMEM_MLP_BYTES>>>(x);

    scan_kernel<<<(NSH + 127)/128, 128>>>();

    conv_kernel<<<NSS, CVT>>>((float*)d_out);
}

// round 11
// speedup vs baseline: 1.9329x; 1.0803x over previous
#include <cuda_runtime.h>
#include <cuda_fp16.h>
#include <math.h>
#include <stdint.h>

#define NTT 730
#define NSS 2000
#define NHH 16
#define NRR 15
#define NSH (NSS*NHH)          // 32000
#define NTS (NTT*NSS)          // 1460000

#define L2E2 2.8853900817779268f   // 2*log2(e)
#define W2S 132                    // uint32 row stride: bank = 4r+c (perfect perm)

// -------- scratch (device globals; no allocation) --------
__device__ __align__(128) float    g_b1T[NSS*256];   // [s][k]
__device__ __align__(128) float    g_b2T[NSS*256];
__device__ __align__(128) float4   g_wc4[256];       // first-layer x-coeffs
__device__ __align__(128) uint32_t g_W2h[48*W2S];    // half2 pairs (2p, 2p+1), [o][p]
__device__ __align__(128) float    g_sbias[48];
__device__ __align__(128) float g_k1[NSH], g_k2[NSH], g_k23[NSH], g_k3[NSH];
__device__ __align__(128) float g_gl[NSH], g_qb[NSH], g_ge1[NSH], g_ge2[NSH];
__device__ __align__(128) float g_cw[NSH*NRR];
__device__ __align__(128) float g_vi[(size_t)NTT*NSH];
__device__ __align__(128) float g_vk[(size_t)NTT*NSH];
__device__ __align__(128) float g_vm[(size_t)NTT*NSH];
__device__ __align__(128) float g_Ps[NTS], g_Pl[NTS], g_E[NTS];
__device__ __align__(128) float g_QT[(size_t)NTT*NSH];

__device__ __forceinline__ float tanh_fast(float x) {
    float e = __expf(2.f * x);
    return 1.f - __fdividef(2.f, e + 1.f);
}
__device__ __forceinline__ float sigmoid_f(float x) {
    return __fdividef(1.f, 1.f + __expf(-x));
}
__device__ __forceinline__ float hsig(float x) {
    return __saturatef(x * (1.f/6.f) + 0.5f);
}
__device__ __forceinline__ float ex2f(float t) {
    float e; asm("ex2.approx.f32 %0, %1;" : "=f"(e) : "f"(t));
    return e;
}
__device__ __forceinline__ uint32_t packh2(float lo, float hi) {
    __half2 h = __floats2half2_rn(lo, hi);     // x = lo half
    return *reinterpret_cast<uint32_t*>(&h);
}
// pack two fp32 args to half2, tanh both in ONE MUFU op; .lo = first arg
__device__ __forceinline__ uint32_t tanh2(float lo, float hi) {
    uint32_t p;
    asm("cvt.rn.f16x2.f32 %0, %1, %2;" : "=r"(p) : "f"(hi), "f"(lo));
    uint32_t r;
    asm("tanh.approx.f16x2 %0, %1;" : "=r"(r) : "r"(p));
    return r;
}
__device__ __forceinline__ void mma16(float* d, const uint32_t* a,
                                      uint32_t b0, uint32_t b1) {
    asm("mma.sync.aligned.m16n8k16.row.col.f32.f16.f16.f32 "
        "{%0,%1,%2,%3}, {%4,%5,%6,%7}, {%8,%9}, {%0,%1,%2,%3};"
        : "+f"(d[0]), "+f"(d[1]), "+f"(d[2]), "+f"(d[3])
        : "r"(a[0]), "r"(a[1]), "r"(a[2]), "r"(a[3]), "r"(b0), "r"(b1));
}

// =====================================================================
// Kernel A: per-basin MLPs (w, wR) + transposed bases
// =====================================================================
__global__ __launch_bounds__(256) void prep_kernel(
    const float* __restrict__ xc,
    const float* __restrict__ fc_W1,  const float* __restrict__ fc_b1,
    const float* __restrict__ fc_W2,  const float* __restrict__ fc_b2,
    const float* __restrict__ fcR_W1, const float* __restrict__ fcR_b1,
    const float* __restrict__ fcR_W2, const float* __restrict__ fcR_b2,
    const float* __restrict__ fcT1_W1,const float* __restrict__ fcT1_b1,
    const float* __restrict__ fcT2_W1,const float* __restrict__ fcT2_b1)
{
    int s = blockIdx.x;
    int tid = threadIdx.x;
    __shared__ float sxc[32];
    __shared__ float sh_h[256], sh_hR[256];
    __shared__ float sh_w[160], sh_wR[240];
    __shared__ float sh_ga[16];

    if (tid < 32) sxc[tid] = xc[s*32 + tid];
    __syncthreads();

    {
        int k = tid;
        float a0 = fc_b1[k], a1 = fcR_b1[k], a2 = fcT1_b1[k], a3 = fcT2_b1[k];
        #pragma unroll
        for (int g = 0; g < 32; g++) {
            float xg = sxc[g];
            a0 += xg * fc_W1 [k*32 + g];
            a1 += xg * fcR_W1[k*32 + g];
            a2 += xg * fcT1_W1[k*33 + 1 + g];
            a3 += xg * fcT2_W1[k*35 + 3 + g];
        }
        sh_h[k]  = tanh_fast(a0);
        sh_hR[k] = tanh_fast(a1);
        g_b1T[s*256 + k] = a2;
        g_b2T[s*256 + k] = a3;
    }
    __syncthreads();

    int warp = tid >> 5, lane = tid & 31;
    for (int o = warp; o < 400; o += 8) {
        float sum = 0.f;
        if (o < 160) {
            const float* w = fc_W2 + o*256;
            for (int k = lane; k < 256; k += 32) sum += sh_h[k] * w[k];
        } else {
            const float* w = fcR_W2 + (o-160)*256;
            for (int k = lane; k < 256; k += 32) sum += sh_hR[k] * w[k];
        }
        #pragma unroll
        for (int off = 16; off; off >>= 1) sum += __shfl_down_sync(0xffffffffu, sum, off);
        if (lane == 0) {
            if (o < 160) sh_w[o] = sum + fc_b2[o];
            else         sh_wR[o-160] = sum + fcR_b2[o-160];
        }
    }
    __syncthreads();

    if (tid < 16) {
        int h = tid, g = s*16 + h;
        g_k1 [g] = sigmoid_f(sh_w[ 16 + h]);
        g_k2 [g] = sigmoid_f(sh_w[ 32 + h]);
        g_k23[g] = sigmoid_f(sh_w[ 48 + h]);
        g_k3 [g] = sigmoid_f(sh_w[ 64 + h]) * 0.1f;
        g_gl [g] = __expf(sh_w[ 80 + h]) * 2.f;
        g_qb [g] = fmaxf(sh_w[112 + h], 0.f);
        g_ge1[g] = fmaxf(sh_w[128 + h], 0.f);
        g_ge2[g] = fmaxf(sh_w[144 + h], 0.f);
        float m = -1e30f;
        #pragma unroll
        for (int j = 0; j < 16; j++) m = fmaxf(m, sh_w[96 + j]);
        float den = 0.f;
        #pragma unroll
        for (int j = 0; j < 16; j++) den += __expf(sh_w[96 + j] - m);
        sh_ga[h] = __fdividef(__expf(sh_w[96 + h] - m), den);
    }
    __syncthreads();

    if (tid < 240) {
        int h = tid / 15, d = tid - h*15;
        g_cw[(s*16 + h)*15 + d] = sh_ga[h] * fmaxf(sh_wR[h*15 + (14 - d)], 0.f);
    }
}

// =====================================================================
// Kernel A2: pack W2 into half2 (2p, 2p+1) pairs [o][p] + wc/bias tables
// =====================================================================
__global__ __launch_bounds__(256) void pack_kernel(
    const float* __restrict__ fcT1_W1, const float* __restrict__ fcT2_W1,
    const float* __restrict__ fcT1_W2, const float* __restrict__ fcT1_b2,
    const float* __restrict__ fcT2_W2, const float* __restrict__ fcT2_b2)
{
    int tid = threadIdx.x;
    {
        int k = tid;
        g_wc4[k] = make_float4(fcT1_W1[k*33],
                               fcT2_W1[k*35],
                               fcT2_W1[k*35 + 1],
                               fcT2_W1[k*35 + 2]);
    }
    if (tid < 48) g_sbias[tid] = (tid < 32) ? fcT1_b2[tid] : fcT2_b2[tid - 32];

    for (int idx = tid; idx < 48*W2S; idx += 256) {
        int o = idx / W2S, p = idx - o*W2S;
        uint32_t v = 0;
        if (p < 128) {
            int k0 = 2*p, k1 = 2*p + 1;
            float w0 = (o < 32) ? fcT1_W2[o*256 + k0] : fcT2_W2[(o-32)*256 + k0];
            float w1 = (o < 32) ? fcT1_W2[o*256 + k1] : fcT2_W2[(o-32)*256 + k1];
            v = packh2(w0, w1);
        }
        g_W2h[idx] = v;
    }
}

// =====================================================================
// Kernel B: fp16 tensor-core MLP (m16n8k16) + f16x2 tanh.
// warp = 32 timesteps x 1 basin.
// =====================================================================
#define SMEM_MLP_F (48*W2S + 256*4 + 8*256*2 + 48)   // 11504 floats
#define SMEM_MLP_BYTES (SMEM_MLP_F*4)                // 46016

__global__ __launch_bounds__(256, 2) void mlp_kernel(const float* __restrict__ x)
{
    extern __shared__ float smem[];
    uint32_t* sW2h  = (uint32_t*)smem;                 // [48*W2S]
    float4*   swc   = (float4*)(smem + 48*W2S);        // [256]
    float2*   sb12  = (float2*)(swc + 256);            // [8][256] {b1,b2}
    float*    sbias = (float*)(sb12 + 8*256);          // [48]

    int tid = threadIdx.x;
    int w = tid >> 5, lane = tid & 31;
    int c = lane & 3, r = lane >> 2;

    {
        const uint4* src = (const uint4*)g_W2h;
        uint4* dst = (uint4*)sW2h;
        for (int i = tid; i < 48*W2S/4; i += 256) dst[i] = src[i];
        swc[tid] = g_wc4[tid];
        if (tid < 48) sbias[tid] = g_sbias[tid];
    }
    int s = blockIdx.y*8 + w;
    {
        const float* b1s = g_b1T + s*256;
        const float* b2s = g_b2T + s*256;
        float2* sb = sb12 + w*256;
        for (int k = lane; k < 256; k += 32)
            sb[k] = make_float2(b1s[k], b2s[k]);
    }
    __syncthreads();

    int t0 = blockIdx.x * 32;
    int tA = t0 + r;
    int tB = tA + 8;
    int tC = tA + 16;
    int tD = tA + 24;             // may overflow on last tile
    bool vD = (tD < NTT);
    int tDl = vD ? tD : (NTT-1);

    const float* xA = x + (size_t)(tA *NSS + s)*6;
    const float* xB = x + (size_t)(tB *NSS + s)*6;
    const float* xC = x + (size_t)(tC *NSS + s)*6;
    const float* xD = x + (size_t)(tDl*NSS + s)*6;
    float PA = xA[0], EA = xA[1], T1A = xA[2], T2A = xA[3], RA = xA[4], LA = xA[5];
    float PB = xB[0], EB = xB[1], T1B = xB[2], T2B = xB[3], RB = xB[4], LB = xB[5];
    float PC = xC[0], EC = xC[1], T1C = xC[2], T2C = xC[3], RC = xC[4], LC = xC[5];
    float PD = xD[0], ED = xD[1], T1D = xD[2], T2D = xD[3], RD = xD[4], LD = xD[5];

    if (c == 0) {
        #pragma unroll
        for (int q = 0; q < 4; q++) {
            float P  = (q==0)?PA :(q==1)?PB :(q==2)?PC :PD;
            float E  = (q==0)?EA :(q==1)?EB :(q==2)?EC :ED;
            float T1 = (q==0)?T1A:(q==1)?T1B:(q==2)?T1C:T1D;
            float T2 = (q==0)?T2A:(q==1)?T2B:(q==2)?T2C:T2D;
            int   t  = (q==0)?tA :(q==1)?tB :(q==2)?tC :tD;
            if (q == 3 && !vD) break;
            float dn = T2 - T1;
            float rr = (T1 + T2) / (dn == 0.f ? 1.f : dn);
            rr = fminf(fmaxf(rr, -1.f), 1.f);
            if ((T1 >= 0.f) || (T2 <= 0.f)) rr = 0.f;
            float vp = 1.f - acosf(rr) / 3.1415f;
            if (T1 >= 0.f) vp = 1.f;
            if (T2 <= 0.f) vp = 0.f;
            int ts = t*NSS + s;
            g_Ps[ts] = P * (1.f - vp);
            g_Pl[ts] = P * vp;
            g_E[ts]  = E;
        }
    }

    float dAB[6][4], dCD[6][4];
    #pragma unroll
    for (int g = 0; g < 6; g++)
        #pragma unroll
        for (int i = 0; i < 4; i++) { dAB[g][i] = 0.f; dCD[g][i] = 0.f; }

    const float* sbf = (const float*)(sb12 + w*256);

    #define A2F(Rv,T1v,T2v,wc,b) fmaf(Rv, (wc).y, fmaf(T1v, (wc).z, fmaf(T2v, (wc).w, (b))))

    #pragma unroll 1
    for (int j = 0; j < 16; j++) {
        int ka = 16*j + 2*c;        // even
        int kb = ka + 8;
        float4 bA = *(const float4*)(sbf + 2*ka);  // {b1[ka],b2[ka],b1[ka+1],b2[ka+1]}
        float4 bB = *(const float4*)(sbf + 2*kb);
        float4 wA0 = swc[ka], wA1 = swc[ka+1];
        float4 wB0 = swc[kb], wB1 = swc[kb+1];

        uint32_t a1AB[4], a1CD[4], a2AB[4], a2CD[4];
        a1AB[0] = tanh2(fmaf(LA, wA0.x, bA.x), fmaf(LA, wA1.x, bA.z));
        a1AB[1] = tanh2(fmaf(LB, wA0.x, bA.x), fmaf(LB, wA1.x, bA.z));
        a1AB[2] = tanh2(fmaf(LA, wB0.x, bB.x), fmaf(LA, wB1.x, bB.z));
        a1AB[3] = tanh2(fmaf(LB, wB0.x, bB.x), fmaf(LB, wB1.x, bB.z));
        a1CD[0] = tanh2(fmaf(LC, wA0.x, bA.x), fmaf(LC, wA1.x, bA.z));
        a1CD[1] = tanh2(fmaf(LD, wA0.x, bA.x), fmaf(LD, wA1.x, bA.z));
        a1CD[2] = tanh2(fmaf(LC, wB0.x, bB.x), fmaf(LC, wB1.x, bB.z));
        a1CD[3] = tanh2(fmaf(LD, wB0.x, bB.x), fmaf(LD, wB1.x, bB.z));

        a2AB[0] = tanh2(A2F(RA,T1A,T2A,wA0,bA.y), A2F(RA,T1A,T2A,wA1,bA.w));
        a2AB[1] = tanh2(A2F(RB,T1B,T2B,wA0,bA.y), A2F(RB,T1B,T2B,wA1,bA.w));
        a2AB[2] = tanh2(A2F(RA,T1A,T2A,wB0,bB.y), A2F(RA,T1A,T2A,wB1,bB.w));
        a2AB[3] = tanh2(A2F(RB,T1B,T2B,wB0,bB.y), A2F(RB,T1B,T2B,wB1,bB.w));
        a2CD[0] = tanh2(A2F(RC,T1C,T2C,wA0,bA.y), A2F(RC,T1C,T2C,wA1,bA.w));
        a2CD[1] = tanh2(A2F(RD,T1D,T2D,wA0,bA.y), A2F(RD,T1D,T2D,wA1,bA.w));
        a2CD[2] = tanh2(A2F(RC,T1C,T2C,wB0,bB.y), A2F(RC,T1C,T2C,wB1,bB.w));
        a2CD[3] = tanh2(A2F(RD,T1D,T2D,wB0,bB.y), A2F(RD,T1D,T2D,wB1,bB.w));

        const uint32_t* Wb = sW2h + 8*j + c;
        #pragma unroll
        for (int g = 0; g < 4; g++) {
            int ro = (8*g + r)*W2S;
            uint32_t b0 = Wb[ro], b1 = Wb[ro + 4];
            mma16(dAB[g], a1AB, b0, b1);
            mma16(dCD[g], a1CD, b0, b1);
        }
        #pragma unroll
        for (int g = 4; g < 6; g++) {
            int ro = (8*g + r)*W2S;
            uint32_t b0 = Wb[ro], b1 = Wb[ro + 4];
            mma16(dAB[g], a2AB, b0, b1);
            mma16(dCD[g], a2CD, b0, b1);
        }
    }
    #undef A2F

    #pragma unroll
    for (int g = 0; g < 6; g++) {
        int o = 8*g + 2*c;
        float bi0 = sbias[o], bi1 = sbias[o+1];
        float2 oA, oB, oC, oD;
        float* arr;
        if (g < 4) {
            oA = make_float2(hsig(dAB[g][0]+bi0), hsig(dAB[g][1]+bi1));
            oB = make_float2(hsig(dAB[g][2]+bi0), hsig(dAB[g][3]+bi1));
            oC = make_float2(hsig(dCD[g][0]+bi0), hsig(dCD[g][1]+bi1));
            oD = make_float2(hsig(dCD[g][2]+bi0), hsig(dCD[g][3]+bi1));
            arr = (g < 2) ? g_vi : g_vk;
        } else {
            oA = make_float2(ex2f((dAB[g][0]+bi0)*L2E2), ex2f((dAB[g][1]+bi1)*L2E2));
            oB = make_float2(ex2f((dAB[g][2]+bi0)*L2E2), ex2f((dAB[g][3]+bi1)*L2E2));
            oC = make_float2(ex2f((dCD[g][0]+bi0)*L2E2), ex2f((dCD[g][1]+bi1)*L2E2));
            oD = make_float2(ex2f((dCD[g][2]+bi0)*L2E2), ex2f((dCD[g][3]+bi1)*L2E2));
            arr = g_vm;
        }
        int h = o & 15;
        size_t off = (size_t)s*16 + h;
        *(float2*)(arr + (size_t)tA*NSH + off) = oA;
        *(float2*)(arr + (size_t)tB*NSH + off) = oB;
        *(float2*)(arr + (size_t)tC*NSH + off) = oC;
        if (vD) *(float2*)(arr + (size_t)tD*NSH + off) = oD;
    }
}

// =====================================================================
// Kernel C: sequential reservoir scan; thread = (s,h).
// EXACT R6 config (measured 189us): SCP=4, t&3 slots under unroll 4,
// six scalar __ldg streams, 128 threads.
// =====================================================================
#define SCP 4
__global__ __launch_bounds__(128) void scan_kernel()
{
    int g = blockIdx.x * 128 + threadIdx.x;
    if (g >= NSH) return;
    int s = g >> 4;
    float k1 = g_k1[g], k2 = g_k2[g], k23 = g_k23[g], k3 = g_k3[g];
    float gl = g_gl[g], qb = g_qb[g], ge1 = g_ge1[g], ge2 = g_ge2[g];
    float S0 = 0.f, Sv = 0.f, S2 = 0.f, S3 = 0.f;

    float b_vi[SCP], b_vk[SCP], b_vm[SCP], b_Ps[SCP], b_Pl[SCP], b_E[SCP];
    #pragma unroll
    for (int i = 0; i < SCP; i++) {
        size_t tg = (size_t)i*NSH + g;
        int ts = i*NSS + s;
        b_vi[i] = __ldg(g_vi + tg);
        b_vk[i] = __ldg(g_vk + tg);
        b_vm[i] = __ldg(g_vm + tg);
        b_Ps[i] = __ldg(g_Ps + ts);
        b_Pl[i] = __ldg(g_Pl + ts);
        b_E [i] = __ldg(g_E  + ts);
    }

    #pragma unroll 4
    for (int t = 0; t < NTT; t++) {
        int slot = t & (SCP-1);
        float Ps = b_Ps[slot], Pl = b_Pl[slot], E = b_E[slot];
        float vi = b_vi[slot], vk = b_vk[slot], vm = b_vm[slot];

        int tn = t + SCP;
        if (tn < NTT) {
            size_t tg = (size_t)tn*NSH + g;
            int ts = tn*NSS + s;
            b_vi[slot] = __ldg(g_vi + tg);
            b_vk[slot] = __ldg(g_vk + tg);
            b_vm[slot] = __ldg(g_vm + tg);
            b_Ps[slot] = __ldg(g_Ps + ts);
            b_Pl[slot] = __ldg(g_Pl + ts);
            b_E [slot] = __ldg(g_E  + ts);
        }

        float H0  = S0 + Ps;
        float qSm = fminf(H0, vm);
        float Hv  = fmaxf(Sv + Pl*(1.f - vi) - E*ge1, 0.f);
        float qv  = Sv * vk;
        float H2  = fmaxf(S2 + qSm + qv - E*ge2 + Pl*vi, 0.f);
        float x1  = H2 - gl;
        float Q1  = (x1 > 0.f) ? exp2f(k1 * __log2f(x1)) : 0.f;
        float q2  = fminf(H2, gl) * k2;
        float Q2  = q2 * (1.f - k23);
        float H3  = S3 + q2 * k23;
        float Q3  = H3 * k3 + qb;

        S0 = H0 - qSm;
        Sv = Hv - qv;
        S2 = H2 - Q1 - q2;
        S3 = H3 - Q3;
        g_QT[(size_t)t*NSH + g] = Q1 + Q2 + Q3;
    }
}

// =====================================================================
// Kernel D: causal depthwise conv + head-sum, register-blocked 4 t/thread
// =====================================================================
#define CVT 192
#define CVS 788
__global__ __launch_bounds__(CVT) void conv_kernel(float* __restrict__ out)
{
    __shared__ float shQ[16*CVS];
    __shared__ float shc[NHH*NRR];
    int s = blockIdx.x;
    int tid = threadIdx.x;

    for (int i = tid; i < 16*CVS; i += CVT) {
        int j = i >> 4, h = i & 15;
        int t = j - 14;
        shQ[h*CVS + j] = (t >= 0 && t < NTT)
            ? g_QT[(size_t)t*NSH + s*16 + h] : 0.f;
    }
    for (int i = tid; i < 240; i += CVT) shc[i] = g_cw[s*240 + i];
    __syncthreads();

    int tb = tid * 4;
    if (tb < NTT) {
        float acc0 = 0.f, acc1 = 0.f, acc2 = 0.f, acc3 = 0.f;
        #pragma unroll
        for (int h = 0; h < 16; h++) {
            const float4* qw = (const float4*)(shQ + h*CVS + tb);
            float wv[20];
            #pragma unroll
            for (int v = 0; v < 5; v++) {
                float4 q4 = qw[v];
                wv[4*v+0] = q4.x; wv[4*v+1] = q4.y; wv[4*v+2] = q4.z; wv[4*v+3] = q4.w;
            }
            #pragma unroll
            for (int d = 0; d < 15; d++) {
                float cc = shc[h*15 + d];
                acc0 += wv[14 - d] * cc;
                acc1 += wv[15 - d] * cc;
                acc2 += wv[16 - d] * cc;
                acc3 += wv[17 - d] * cc;
            }
        }
        out[(tb+0)*NSS + s] = acc0;
        if (tb+1 < NTT) out[(tb+1)*NSS + s] = acc1;
        if (tb+2 < NTT) out[(tb+2)*NSS + s] = acc2;
        if (tb+3 < NTT) out[(tb+3)*NSS + s] = acc3;
    }
}

// =====================================================================
extern "C" void kernel_launch(void* const* d_in, const int* in_sizes, int n_in,
                              void* d_out, int out_size)
{
    const float* x       = (const float*)d_in[0];
    const float* xc      = (const float*)d_in[1];
    const float* fc_W1   = (const float*)d_in[2];
    const float* fc_b1   = (const float*)d_in[3];
    const float* fc_W2   = (const float*)d_in[4];
    const float* fc_b2   = (const float*)d_in[5];
    const float* fcR_W1  = (const float*)d_in[6];
    const float* fcR_b1  = (const float*)d_in[7];
    const float* fcR_W2  = (const float*)d_in[8];
    const float* fcR_b2  = (const float*)d_in[9];
    const float* fcT1_W1 = (const float*)d_in[10];
    const float* fcT1_b1 = (const float*)d_in[11];
    const float* fcT1_W2 = (const float*)d_in[12];
    const float* fcT1_b2 = (const float*)d_in[13];
    const float* fcT2_W1 = (const float*)d_in[14];
    const float* fcT2_b1 = (const float*)d_in[15];
    const float* fcT2_W2 = (const float*)d_in[16];
    const float* fcT2_b2 = (const float*)d_in[17];

    cudaFuncSetAttribute(mlp_kernel, cudaFuncAttributeMaxDynamicSharedMemorySize,
                         SMEM_MLP_BYTES);

    prep_kernel<<<NSS, 256>>>(xc, fc_W1, fc_b1, fc_W2, fc_b2,
                              fcR_W1, fcR_b1, fcR_W2, fcR_b2,
                              fcT1_W1, fcT1_b1, fcT2_W1, fcT2_b1);

    pack_kernel<<<1, 256>>>(fcT1_W1, fcT2_W1, fcT1_W2, fcT1_b2, fcT2_W2, fcT2_b2);

    dim3 gB((NTT + 31)/32, NSS/8);
    mlp_kernel<<<gB, 256, SMEM_MLP_BYTES>>>(x);

    scan_kernel<<<(NSH + 127)/128, 128>>>();

    conv_kernel<<<NSS, CVT>>>((float*)d_out);
}